// round 5
// baseline (speedup 1.0000x reference)
#include <cuda_runtime.h>
#include <math.h>

// Problem constants
#define BB 256
#define HH 512
#define LLAYERS 3
#define TSTEPS 200
#define VV 100

typedef unsigned long long ull;

// ---------------- device scratch (no allocations allowed) ----------------
__device__ __align__(16) float g_wcomb[3u * 2048u * 1024u];   // 25.2 MB  [l][(j*4+gate)][k(x||h)]
__device__ __align__(16) float g_bcomb[3 * 2048];             // b_ih + b_hh, gate-interleaved
__device__ __align__(16) float g_h[2][3 * 256 * 512];         // double-buffered hidden states
__device__ __align__(16) float g_c[2][3 * 256 * 512];         // double-buffered cell states
__device__ __align__(16) float g_feat1[256 * 512];
__device__ __align__(16) float g_res[256u * 200u * 512u];     // [b][t][h]  105 MB
__device__ __align__(16) float g_hmid[51200u * 1024u];        // 210 MB

// ---------------- f32x2 packed helpers (Blackwell FFMA2 path) ----------------
__device__ __forceinline__ ull pk2(float a, float b) {
    ull r; asm("mov.b64 %0, {%1, %2};" : "=l"(r) : "f"(a), "f"(b)); return r;
}
__device__ __forceinline__ float2 upk2(ull v) {
    float2 r; asm("mov.b64 {%0, %1}, %2;" : "=f"(r.x), "=f"(r.y) : "l"(v)); return r;
}
__device__ __forceinline__ void fma2(ull& d, ull a, ull b) {
    asm("fma.rn.f32x2 %0, %1, %2, %0;" : "+l"(d) : "l"(a), "l"(b));
}

__device__ __forceinline__ float sigf(float x) { return 1.0f / (1.0f + expf(-x)); }
__device__ __forceinline__ float geluf(float x) { return 0.5f * x * (1.0f + erff(x * 0.70710678118654752f)); }

// ---------------- 64x64 tile accumulation core (256 threads, 2 warps/SMSP) ----
// Thread (tx = tid&15, ty = tid>>4) owns rows rbase+ty*4..+3 (as 2 packed
// pairs) x cols nbase+tx*4..+3.  acc[p][c]: pair p = rows (ty*4+2p, +1).
// A: rows rbase..rbase+63, row stride lda (lda==0 => broadcast single row).
// B: output-col n reads B[n*ldb + k], k in [0,K). K must be a multiple of 32.
// smem: 2*32*64 floats (As k-major [32][64], Bs k-major [32][64]).
template<bool GUARDB>
__device__ __forceinline__ void gemm_acc(ull acc[2][4],
                                         const float* __restrict__ A, int lda,
                                         const float* __restrict__ B, int ldb,
                                         int K, int rbase, int nbase, int nlimit,
                                         float* smem)
{
    float* As = smem;
    float* Bs = smem + 32 * 64;
    const int tid = threadIdx.x;
    const int tx = tid & 15, ty = tid >> 4;
    const int nchunks = K >> 5;

    float4 pa[2], pb[2];
    // prefetch chunk 0 (512 float4 per tile / 256 threads = 2 each)
#pragma unroll
    for (int i = 0; i < 2; ++i) {
        int idx = i * 256 + tid;          // 0..511
        int row = idx >> 3, kg = idx & 7; // row in tile, float4 group in chunk
        pa[i] = *(const float4*)(A + (size_t)(rbase + row) * lda + kg * 4);
        int n = nbase + row;
        if (GUARDB && n >= nlimit) pb[i] = make_float4(0.f, 0.f, 0.f, 0.f);
        else                       pb[i] = *(const float4*)(B + (size_t)n * ldb + kg * 4);
    }

    for (int kc = 0; kc < nchunks; ++kc) {
        __syncthreads();   // previous chunk's consumers done
#pragma unroll
        for (int i = 0; i < 2; ++i) {
            int idx = i * 256 + tid;
            int row = idx >> 3, kg = idx & 7;
            As[(kg * 4 + 0) * 64 + row] = pa[i].x;
            As[(kg * 4 + 1) * 64 + row] = pa[i].y;
            As[(kg * 4 + 2) * 64 + row] = pa[i].z;
            As[(kg * 4 + 3) * 64 + row] = pa[i].w;
            Bs[(kg * 4 + 0) * 64 + row] = pb[i].x;
            Bs[(kg * 4 + 1) * 64 + row] = pb[i].y;
            Bs[(kg * 4 + 2) * 64 + row] = pb[i].z;
            Bs[(kg * 4 + 3) * 64 + row] = pb[i].w;
        }
        __syncthreads();

        if (kc + 1 < nchunks) {           // prefetch next chunk (overlaps compute)
            int k0 = (kc + 1) * 32;
#pragma unroll
            for (int i = 0; i < 2; ++i) {
                int idx = i * 256 + tid;
                int row = idx >> 3, kg = idx & 7;
                pa[i] = *(const float4*)(A + (size_t)(rbase + row) * lda + k0 + kg * 4);
                int n = nbase + row;
                if (GUARDB && n >= nlimit) pb[i] = make_float4(0.f, 0.f, 0.f, 0.f);
                else                       pb[i] = *(const float4*)(B + (size_t)n * ldb + k0 + kg * 4);
            }
        }

#pragma unroll
        for (int k = 0; k < 32; ++k) {
            ull a0 = *(const ull*)&As[k * 64 + ty * 4 + 0];
            ull a1 = *(const ull*)&As[k * 64 + ty * 4 + 2];
            float4 wv = *(const float4*)&Bs[k * 64 + tx * 4];
            ull w0 = pk2(wv.x, wv.x), w1 = pk2(wv.y, wv.y);
            ull w2 = pk2(wv.z, wv.z), w3 = pk2(wv.w, wv.w);
            fma2(acc[0][0], a0, w0); fma2(acc[0][1], a0, w1); fma2(acc[0][2], a0, w2); fma2(acc[0][3], a0, w3);
            fma2(acc[1][0], a1, w0); fma2(acc[1][1], a1, w1); fma2(acc[1][2], a1, w2); fma2(acc[1][3], a1, w3);
        }
    }
    __syncthreads();  // smem free for next use
}

// ---------------- generic 64x64-tiled GEMM: C = epi(A*B^T + bias) ----------------
// EPI: 0 = none, 1 = exact gelu
template<int EPI>
__global__ __launch_bounds__(256) void k_gemm64(const float* __restrict__ A, int lda,
                                                const float* __restrict__ B, int ldb,
                                                const float* __restrict__ bias,
                                                float* __restrict__ C, int ldc, int K)
{
    __shared__ float smem[2 * 32 * 64];
    ull acc[2][4] = {};
    const int rbase = blockIdx.y * 64;
    const int nbase = blockIdx.x * 64;
    gemm_acc<false>(acc, A, lda, B, ldb, K, rbase, nbase, 1 << 30, smem);

    const int tx = threadIdx.x & 15, ty = threadIdx.x >> 4;
#pragma unroll
    for (int p = 0; p < 2; ++p) {
        int r = rbase + ty * 4 + 2 * p;
#pragma unroll
        for (int c = 0; c < 4; ++c) {
            int n = nbase + tx * 4 + c;
            float2 v = upk2(acc[p][c]);
            float bz = bias[n];
            float x0 = v.x + bz, x1 = v.y + bz;
            if (EPI == 1) { x0 = geluf(x0); x1 = geluf(x1); }
            C[(size_t)r * ldc + n]       = x0;
            C[(size_t)(r + 1) * ldc + n] = x1;
        }
    }
}

// ---------------- final projection with transposed store out[b][v][t] ----------------
__global__ __launch_bounds__(256) void k_proj2(const float* __restrict__ A,   // g_hmid [51200][1024]
                                               const float* __restrict__ W2,  // [100][1024]
                                               const float* __restrict__ b2,
                                               float* __restrict__ out)
{
    __shared__ float smem[2 * 32 * 64];
    ull acc[2][4] = {};
    const int rbase = blockIdx.y * 64;
    const int nbase = blockIdx.x * 64;
    gemm_acc<true>(acc, A, 1024, W2, 1024, 1024, rbase, nbase, VV, smem);

    const int tx = threadIdx.x & 15, ty = threadIdx.x >> 4;
#pragma unroll
    for (int p = 0; p < 2; ++p) {
        int r0 = rbase + ty * 4 + 2 * p;
#pragma unroll
        for (int c = 0; c < 4; ++c) {
            int v = nbase + tx * 4 + c;
            if (v >= VV) continue;
            float2 val = upk2(acc[p][c]);
            float bz = b2[v];
#pragma unroll
            for (int q = 0; q < 2; ++q) {
                int r = r0 + q;
                int b = r / TSTEPS, t = r - b * TSTEPS;
                out[((size_t)b * VV + v) * TSTEPS + t] = (q ? val.y : val.x) + bz;
            }
        }
    }
}

// ---------------- weight reorder + c-state zero ----------------
// g_wcomb[l][j*4+gate][k] = k<512 ? w_ih[l][gate*512+j][k] : w_hh[l][gate*512+j][k-512]
__global__ void k_prep(const float* __restrict__ w_ih, const float* __restrict__ w_hh,
                       const float* __restrict__ b_ih, const float* __restrict__ b_hh)
{
    const size_t stride = (size_t)gridDim.x * blockDim.x;
    const size_t tid = (size_t)blockIdx.x * blockDim.x + threadIdx.x;
    const size_t nf4 = (size_t)3 * 2048 * 1024 / 4;
    for (size_t i = tid; i < nf4; i += stride) {
        size_t f = i * 4;
        int k  = (int)(f & 1023);
        size_t np = f >> 10;               // l*2048 + n'
        int l  = (int)(np >> 11);
        int n2 = (int)(np & 2047);
        int jj = n2 >> 2, g = n2 & 3;
        int n  = g * 512 + jj;
        const float* src = (k < 512) ? (w_ih + ((size_t)l * 2048 + n) * 512 + k)
                                     : (w_hh + ((size_t)l * 2048 + n) * 512 + (k - 512));
        *(float4*)&g_wcomb[f] = *(const float4*)src;
    }
    for (size_t i = tid; i < 3 * 2048; i += stride) {
        int l = (int)(i >> 11), n2 = (int)(i & 2047);
        int jj = n2 >> 2, g = n2 & 3;
        int n = g * 512 + jj;
        g_bcomb[i] = b_ih[(size_t)l * 2048 + n] + b_hh[(size_t)l * 2048 + n];
    }
    for (size_t i = tid; i < (size_t)3 * 256 * 512; i += stride) g_c[1][i] = 0.f;
}

// replicate h0 (written into g_h[1] layer 0) to layers 1 and 2
__global__ void k_repl()
{
    const int stride = gridDim.x * blockDim.x;
    for (int i = blockIdx.x * blockDim.x + threadIdx.x; i < 256 * 512; i += stride) {
        float v = g_h[1][i];
        g_h[1][256 * 512 + i]     = v;
        g_h[1][2 * 256 * 512 + i] = v;
    }
}

// ---------------- one recurrent (t, l) iteration: fused GEMM + LSTM cell ----------------
// Launched 600 times as separate graph nodes; stream order provides all
// inter-iteration synchronization.
__global__ __launch_bounds__(256) void k_step(const float* __restrict__ embed,
                                              const int* __restrict__ sidx,
                                              int t, int l)
{
    __shared__ float smem[2 * 32 * 64];
    const int mt = blockIdx.x >> 5;          // 0..3  (M tile: 64 batch rows)
    const int jt = blockIdx.x & 31;          // 0..31 (16 hidden units x 4 gates)
    const int rbase = mt * 64;
    const int nbase = jt * 64;
    const int tx = threadIdx.x & 15, ty = threadIdx.x >> 4;

    const int wpar = t & 1, rpar = wpar ^ 1;
    const float* W = g_wcomb + (size_t)l * 2048 * 1024;

    const float* xsrc; int xlda;
    if (l == 0) {
        if (t == 0) { xsrc = embed + (size_t)(*sidx) * 512; xlda = 0; }  // broadcast <sos>
        else        { xsrc = g_h[rpar] + 2 * 256 * 512; xlda = 512; }
    } else {
        xsrc = g_h[wpar] + (size_t)(l - 1) * 256 * 512; xlda = 512;
    }
    const float* hsrc = g_h[rpar] + (size_t)l * 256 * 512;

    ull acc[2][4] = {};
    gemm_acc<false>(acc, xsrc, xlda, W,       1024, 512, rbase, nbase, 1 << 30, smem);
    gemm_acc<false>(acc, hsrc, 512,  W + 512, 1024, 512, rbase, nbase, 1 << 30, smem);

    // fused LSTM cell epilogue: this thread owns hidden unit j for 4 batch rows
    const int j = jt * 16 + tx;
    const float bi = g_bcomb[l * 2048 + j * 4 + 0];
    const float bf = g_bcomb[l * 2048 + j * 4 + 1];
    const float bg = g_bcomb[l * 2048 + j * 4 + 2];
    const float bo = g_bcomb[l * 2048 + j * 4 + 3];
    const float* cprev = g_c[rpar] + (size_t)l * 256 * 512;
    float* cnew = g_c[wpar] + (size_t)l * 256 * 512;
    float* hnew = g_h[wpar] + (size_t)l * 256 * 512;

#pragma unroll
    for (int p = 0; p < 2; ++p) {
        float2 gi = upk2(acc[p][0]);
        float2 gf = upk2(acc[p][1]);
        float2 gg = upk2(acc[p][2]);
        float2 go = upk2(acc[p][3]);
        int r0 = rbase + ty * 4 + 2 * p;
#pragma unroll
        for (int q = 0; q < 2; ++q) {
            int r = r0 + q;
            float I = sigf((q ? gi.y : gi.x) + bi);
            float F = sigf((q ? gf.y : gf.x) + bf);
            float G = tanhf((q ? gg.y : gg.x) + bg);
            float O = sigf((q ? go.y : go.x) + bo);
            float cp = cprev[(size_t)r * 512 + j];
            float cn = F * cp + I * G;
            float hn = O * tanhf(cn);
            cnew[(size_t)r * 512 + j] = cn;
            hnew[(size_t)r * 512 + j] = hn;
            if (l == 2) g_res[((size_t)r * TSTEPS + t) * 512 + j] = hn;
        }
    }
}

// ---------------- host launcher ----------------
extern "C" void kernel_launch(void* const* d_in, const int* in_sizes, int n_in,
                              void* d_out, int out_size)
{
    (void)in_sizes; (void)n_in; (void)out_size;
    const float* feat  = (const float*)d_in[0];
    const float* vw    = (const float*)d_in[1];
    const float* vb    = (const float*)d_in[2];
    const float* embed = (const float*)d_in[3];
    const float* w_ih  = (const float*)d_in[4];
    const float* w_hh  = (const float*)d_in[5];
    const float* b_ih  = (const float*)d_in[6];
    const float* b_hh  = (const float*)d_in[7];
    const float* pw1   = (const float*)d_in[8];
    const float* pb1   = (const float*)d_in[9];
    const float* pw2   = (const float*)d_in[10];
    const float* pb2   = (const float*)d_in[11];
    const int*   sidx  = (const int*)d_in[12];
    float* out = (float*)d_out;

    float *s_feat1, *s_h, *s_res, *s_hmid;
    cudaGetSymbolAddress((void**)&s_feat1, g_feat1);
    cudaGetSymbolAddress((void**)&s_h, g_h);
    cudaGetSymbolAddress((void**)&s_res, g_res);
    cudaGetSymbolAddress((void**)&s_hmid, g_hmid);
    float* s_h1 = s_h + (size_t)3 * 256 * 512;   // g_h[1]

    // 1) reorder weights, combine biases, zero initial cell state
    k_prep<<<512, 256>>>(w_ih, w_hh, b_ih, b_hh);
    // 2) feat1 = feat @ Vw^T + vb
    k_gemm64<0><<<dim3(8, 4), 256>>>(feat, 512, vw, 512, vb, s_feat1, 512, 512);
    // 3) h0 = feat1 @ Vw^T + vb  -> g_h[1] layer 0
    k_gemm64<0><<<dim3(8, 4), 256>>>(s_feat1, 512, vw, 512, vb, s_h1, 512, 512);
    // 4) replicate h0 to layers 1, 2
    k_repl<<<256, 256>>>();
    // 5) 600 recurrent iterations, one launch each (stream order = sync)
    for (int t = 0; t < TSTEPS; ++t)
        for (int l = 0; l < LLAYERS; ++l)
            k_step<<<128, 256>>>(embed, sidx, t, l);
    // 6) hmid = gelu(res @ W1^T + b1)
    k_gemm64<1><<<dim3(16, 800), 256>>>(s_res, 512, pw1, 512, pb1, s_hmid, 1024, 512);
    // 7) logits -> out[b][v][t]
    k_proj2<<<dim3(2, 800), 256>>>(s_hmid, pw2, pb2, out);
}

// round 6
// speedup vs baseline: 1.9924x; 1.9924x over previous
#include <cuda_runtime.h>
#include <cuda_bf16.h>
#include <math.h>

// Problem constants
#define BB 256
#define HH 512
#define LLAYERS 3
#define TSTEPS 200
#define VV 100
#define BH (256 * 512)

typedef unsigned long long ull;
typedef unsigned int uint;

// ---------------- device scratch (no allocations allowed) ----------------
__device__ __align__(16) __nv_bfloat16 g_whi[3u * 2048u * 1024u];  // weights hi, [l][(jj*4+gate)][k(x||h)]
__device__ __align__(16) __nv_bfloat16 g_wlo[3u * 2048u * 1024u];  // weights lo
__device__ __align__(16) float g_bcomb[3 * 2048];                  // b_ih + b_hh, gate-interleaved
__device__ __align__(16) __nv_bfloat16 g_ahi[2 * 3 * BH];          // activations hi (double-buffered, [buf*3+l])
__device__ __align__(16) __nv_bfloat16 g_alo[2 * 3 * BH];          // activations lo
__device__ __align__(16) __nv_bfloat16 g_ehi[512];                 // split embed <sos> row
__device__ __align__(16) __nv_bfloat16 g_elo[512];
__device__ __align__(16) float g_c[2][3 * BH];                     // cell states fp32
__device__ __align__(16) float g_feat1[BB * HH];
__device__ __align__(16) float g_h0[BB * HH];
__device__ __align__(16) float g_res[256u * 200u * 512u];          // [b][t][h]
__device__ __align__(16) float g_hmid[51200u * 1024u];

// ---------------- helpers ----------------
__device__ __forceinline__ ull pk2(float a, float b) {
    ull r; asm("mov.b64 %0, {%1, %2};" : "=l"(r) : "f"(a), "f"(b)); return r;
}
__device__ __forceinline__ float2 upk2(ull v) {
    float2 r; asm("mov.b64 {%0, %1}, %2;" : "=f"(r.x), "=f"(r.y) : "l"(v)); return r;
}
__device__ __forceinline__ void fma2(ull& d, ull a, ull b) {
    asm("fma.rn.f32x2 %0, %1, %2, %0;" : "+l"(d) : "l"(a), "l"(b));
}
__device__ __forceinline__ float sigf(float x) { return 1.0f / (1.0f + expf(-x)); }
__device__ __forceinline__ float geluf(float x) { return 0.5f * x * (1.0f + erff(x * 0.70710678118654752f)); }

__device__ __forceinline__ void mma16816(float d[4], const uint a[4], const uint b[2]) {
    asm volatile(
        "mma.sync.aligned.m16n8k16.row.col.f32.bf16.bf16.f32 "
        "{%0,%1,%2,%3}, {%4,%5,%6,%7}, {%8,%9}, {%0,%1,%2,%3};"
        : "+f"(d[0]), "+f"(d[1]), "+f"(d[2]), "+f"(d[3])
        : "r"(a[0]), "r"(a[1]), "r"(a[2]), "r"(a[3]), "r"(b[0]), "r"(b[1]));
}

// ================= fp32 path (init + projection), from working R4 =================
template<bool GUARDB>
__device__ __forceinline__ void gemm_acc(ull acc[2][4],
                                         const float* __restrict__ A, int lda,
                                         const float* __restrict__ B, int ldb,
                                         int K, int rbase, int nbase, int nlimit,
                                         float* smem)
{
    float* As = smem;
    float* Bs = smem + 32 * 64;
    const int tid = threadIdx.x;
    const int tx = tid & 15, ty = tid >> 4;
    const int nchunks = K >> 5;

    float4 pa[2], pb[2];
#pragma unroll
    for (int i = 0; i < 2; ++i) {
        int idx = i * 256 + tid;
        int row = idx >> 3, kg = idx & 7;
        pa[i] = *(const float4*)(A + (size_t)(rbase + row) * lda + kg * 4);
        int n = nbase + row;
        if (GUARDB && n >= nlimit) pb[i] = make_float4(0.f, 0.f, 0.f, 0.f);
        else                       pb[i] = *(const float4*)(B + (size_t)n * ldb + kg * 4);
    }

    for (int kc = 0; kc < nchunks; ++kc) {
        __syncthreads();
#pragma unroll
        for (int i = 0; i < 2; ++i) {
            int idx = i * 256 + tid;
            int row = idx >> 3, kg = idx & 7;
            As[(kg * 4 + 0) * 64 + row] = pa[i].x;
            As[(kg * 4 + 1) * 64 + row] = pa[i].y;
            As[(kg * 4 + 2) * 64 + row] = pa[i].z;
            As[(kg * 4 + 3) * 64 + row] = pa[i].w;
            Bs[(kg * 4 + 0) * 64 + row] = pb[i].x;
            Bs[(kg * 4 + 1) * 64 + row] = pb[i].y;
            Bs[(kg * 4 + 2) * 64 + row] = pb[i].z;
            Bs[(kg * 4 + 3) * 64 + row] = pb[i].w;
        }
        __syncthreads();

        if (kc + 1 < nchunks) {
            int k0 = (kc + 1) * 32;
#pragma unroll
            for (int i = 0; i < 2; ++i) {
                int idx = i * 256 + tid;
                int row = idx >> 3, kg = idx & 7;
                pa[i] = *(const float4*)(A + (size_t)(rbase + row) * lda + k0 + kg * 4);
                int n = nbase + row;
                if (GUARDB && n >= nlimit) pb[i] = make_float4(0.f, 0.f, 0.f, 0.f);
                else                       pb[i] = *(const float4*)(B + (size_t)n * ldb + k0 + kg * 4);
            }
        }

#pragma unroll
        for (int k = 0; k < 32; ++k) {
            ull a0 = *(const ull*)&As[k * 64 + ty * 4 + 0];
            ull a1 = *(const ull*)&As[k * 64 + ty * 4 + 2];
            float4 wv = *(const float4*)&Bs[k * 64 + tx * 4];
            ull w0 = pk2(wv.x, wv.x), w1 = pk2(wv.y, wv.y);
            ull w2 = pk2(wv.z, wv.z), w3 = pk2(wv.w, wv.w);
            fma2(acc[0][0], a0, w0); fma2(acc[0][1], a0, w1); fma2(acc[0][2], a0, w2); fma2(acc[0][3], a0, w3);
            fma2(acc[1][0], a1, w0); fma2(acc[1][1], a1, w1); fma2(acc[1][2], a1, w2); fma2(acc[1][3], a1, w3);
        }
    }
    __syncthreads();
}

template<int EPI>
__global__ __launch_bounds__(256) void k_gemm64(const float* __restrict__ A, int lda,
                                                const float* __restrict__ B, int ldb,
                                                const float* __restrict__ bias,
                                                float* __restrict__ C, int ldc, int K)
{
    __shared__ float smem[2 * 32 * 64];
    ull acc[2][4] = {};
    const int rbase = blockIdx.y * 64;
    const int nbase = blockIdx.x * 64;
    gemm_acc<false>(acc, A, lda, B, ldb, K, rbase, nbase, 1 << 30, smem);

    const int tx = threadIdx.x & 15, ty = threadIdx.x >> 4;
#pragma unroll
    for (int p = 0; p < 2; ++p) {
        int r = rbase + ty * 4 + 2 * p;
#pragma unroll
        for (int c = 0; c < 4; ++c) {
            int n = nbase + tx * 4 + c;
            float2 v = upk2(acc[p][c]);
            float bz = bias[n];
            float x0 = v.x + bz, x1 = v.y + bz;
            if (EPI == 1) { x0 = geluf(x0); x1 = geluf(x1); }
            C[(size_t)r * ldc + n]       = x0;
            C[(size_t)(r + 1) * ldc + n] = x1;
        }
    }
}

__global__ __launch_bounds__(256) void k_proj2(const float* __restrict__ A,
                                               const float* __restrict__ W2,
                                               const float* __restrict__ b2,
                                               float* __restrict__ out)
{
    __shared__ float smem[2 * 32 * 64];
    ull acc[2][4] = {};
    const int rbase = blockIdx.y * 64;
    const int nbase = blockIdx.x * 64;
    gemm_acc<true>(acc, A, 1024, W2, 1024, 1024, rbase, nbase, VV, smem);

    const int tx = threadIdx.x & 15, ty = threadIdx.x >> 4;
#pragma unroll
    for (int p = 0; p < 2; ++p) {
        int r0 = rbase + ty * 4 + 2 * p;
#pragma unroll
        for (int c = 0; c < 4; ++c) {
            int v = nbase + tx * 4 + c;
            if (v >= VV) continue;
            float2 val = upk2(acc[p][c]);
            float bz = b2[v];
#pragma unroll
            for (int q = 0; q < 2; ++q) {
                int r = r0 + q;
                int b = r / TSTEPS, t = r - b * TSTEPS;
                out[((size_t)b * VV + v) * TSTEPS + t] = (q ? val.y : val.x) + bz;
            }
        }
    }
}

// ---------------- prep: split weights to bf16 hi/lo, biases, embed, zero c ----------------
__global__ void k_prep(const float* __restrict__ w_ih, const float* __restrict__ w_hh,
                       const float* __restrict__ b_ih, const float* __restrict__ b_hh,
                       const float* __restrict__ embed, const int* __restrict__ sidx)
{
    const size_t stride = (size_t)gridDim.x * blockDim.x;
    const size_t tid = (size_t)blockIdx.x * blockDim.x + threadIdx.x;
    const size_t nel = (size_t)3 * 2048 * 1024;
    for (size_t i = tid; i < nel; i += stride) {
        int k  = (int)(i & 1023);
        size_t np = i >> 10;
        int l  = (int)(np >> 11);
        int n2 = (int)(np & 2047);
        int jj = n2 >> 2, g = n2 & 3;
        int n  = g * 512 + jj;
        float w = (k < 512) ? w_ih[((size_t)l * 2048 + n) * 512 + k]
                            : w_hh[((size_t)l * 2048 + n) * 512 + (k - 512)];
        __nv_bfloat16 hi = __float2bfloat16(w);
        g_whi[i] = hi;
        g_wlo[i] = __float2bfloat16(w - __bfloat162float(hi));
    }
    for (size_t i = tid; i < 3 * 2048; i += stride) {
        int l = (int)(i >> 11), n2 = (int)(i & 2047);
        int jj = n2 >> 2, g = n2 & 3;
        int n = g * 512 + jj;
        g_bcomb[i] = b_ih[(size_t)l * 2048 + n] + b_hh[(size_t)l * 2048 + n];
    }
    for (size_t i = tid; i < 512; i += stride) {
        float e = embed[(size_t)(*sidx) * 512 + i];
        __nv_bfloat16 hi = __float2bfloat16(e);
        g_ehi[i] = hi;
        g_elo[i] = __float2bfloat16(e - __bfloat162float(hi));
    }
    for (size_t i = tid; i < (size_t)3 * BH; i += stride) g_c[1][i] = 0.f;
}

// split h0 fp32 -> hi/lo for all 3 layers of activation buffer 1
__global__ void k_split0()
{
    const int stride = gridDim.x * blockDim.x;
    for (int i = blockIdx.x * blockDim.x + threadIdx.x; i < BH; i += stride) {
        float v = g_h0[i];
        __nv_bfloat16 hi = __float2bfloat16(v);
        __nv_bfloat16 lo = __float2bfloat16(v - __bfloat162float(hi));
#pragma unroll
        for (int l = 0; l < 3; ++l) {
            g_ahi[(3 + l) * BH + i] = hi;
            g_alo[(3 + l) * BH + i] = lo;
        }
    }
}

// ---------------- recurrent step: bf16 split-product tensor-core GEMM + fused cell ----
// CTA tile M=64 x N=64, K=1024 (x||h).  128 threads = 4 warps (2M x 2N),
// warp tile 32x32 = 2 m16-frags x 4 n8-frags, mma.m16n8k16.
// SMEM rows padded to 72 bf16 (36 words) -> fragment LDS provably conflict-free.
#define SPAD 72
__global__ __launch_bounds__(128) void k_step(int t, int l)
{
    __shared__ __nv_bfloat16 sAhi[64 * SPAD];
    __shared__ __nv_bfloat16 sAlo[64 * SPAD];
    __shared__ __nv_bfloat16 sWhi[64 * SPAD];
    __shared__ __nv_bfloat16 sWlo[64 * SPAD];

    const int tid = threadIdx.x;
    const int wid = tid >> 5, lane = tid & 31;
    const int gid = lane >> 2, tg = lane & 3;
    const int wm = wid >> 1, wn = wid & 1;
    const int mt = blockIdx.x >> 5, jt = blockIdx.x & 31;
    const int rbase = mt * 64, nbase = jt * 64;
    const int wpar = t & 1, rpar = wpar ^ 1;

    // weight rows for this CTA
    const __nv_bfloat16* Whi = g_whi + ((size_t)l * 2048 + nbase) * 1024;
    const __nv_bfloat16* Wlo = g_wlo + ((size_t)l * 2048 + nbase) * 1024;

    // A sources: x-part (k 0..511) and h-part (k 512..1023)
    const __nv_bfloat16 *Axh, *Axl; int ldax;
    if (l == 0) {
        if (t == 0) { Axh = g_ehi; Axl = g_elo; ldax = 0; }
        else        { Axh = g_ahi + (size_t)(rpar * 3 + 2) * BH + (size_t)rbase * 512;
                      Axl = g_alo + (size_t)(rpar * 3 + 2) * BH + (size_t)rbase * 512; ldax = 512; }
    } else {
        Axh = g_ahi + (size_t)(wpar * 3 + l - 1) * BH + (size_t)rbase * 512;
        Axl = g_alo + (size_t)(wpar * 3 + l - 1) * BH + (size_t)rbase * 512; ldax = 512;
    }
    const __nv_bfloat16* Ahh = g_ahi + (size_t)(rpar * 3 + l) * BH + (size_t)rbase * 512;
    const __nv_bfloat16* All = g_alo + (size_t)(rpar * 3 + l) * BH + (size_t)rbase * 512;

    float acc[2][4][4] = {};

    uint4 pah[4], pal[4], pwh[4], pwl[4];
    // prefetch chunk 0 (A: x-part)
#pragma unroll
    for (int i = 0; i < 4; ++i) {
        int idx = i * 128 + tid;
        int row = idx >> 3, kg = idx & 7;   // 64 rows x 8 groups of 8 bf16
        int ke = kg * 8;                    // element offset in chunk
        pah[i] = *(const uint4*)(Axh + (size_t)row * ldax + ke);
        pal[i] = *(const uint4*)(Axl + (size_t)row * ldax + ke);
        pwh[i] = *(const uint4*)(Whi + (size_t)row * 1024 + ke);
        pwl[i] = *(const uint4*)(Wlo + (size_t)row * 1024 + ke);
    }

    for (int kc = 0; kc < 16; ++kc) {
        __syncthreads();
#pragma unroll
        for (int i = 0; i < 4; ++i) {
            int idx = i * 128 + tid;
            int row = idx >> 3, kg = idx & 7;
            int so = row * SPAD + kg * 8;
            *(uint4*)&sAhi[so] = pah[i];
            *(uint4*)&sAlo[so] = pal[i];
            *(uint4*)&sWhi[so] = pwh[i];
            *(uint4*)&sWlo[so] = pwl[i];
        }
        __syncthreads();

        if (kc + 1 < 16) {
            int kn = kc + 1;
            const __nv_bfloat16 *Ah, *Al; int lda_, koff;
            if (kn < 8) { Ah = Axh; Al = Axl; lda_ = ldax; koff = kn * 64; }
            else        { Ah = Ahh; Al = All; lda_ = 512;  koff = kn * 64 - 512; }
            int kW = kn * 64;
#pragma unroll
            for (int i = 0; i < 4; ++i) {
                int idx = i * 128 + tid;
                int row = idx >> 3, kg = idx & 7;
                int ke = kg * 8;
                pah[i] = *(const uint4*)(Ah + (size_t)row * lda_ + koff + ke);
                pal[i] = *(const uint4*)(Al + (size_t)row * lda_ + koff + ke);
                pwh[i] = *(const uint4*)(Whi + (size_t)row * 1024 + kW + ke);
                pwl[i] = *(const uint4*)(Wlo + (size_t)row * 1024 + kW + ke);
            }
        }

#pragma unroll
        for (int k4 = 0; k4 < 4; ++k4) {
            int kb = k4 * 16 + tg * 2;
            uint ahi[2][4], alo[2][4];
#pragma unroll
            for (int mf = 0; mf < 2; ++mf) {
                int r = wm * 32 + mf * 16 + gid;
                int base = r * SPAD + kb;
                ahi[mf][0] = *(const uint*)&sAhi[base];
                ahi[mf][1] = *(const uint*)&sAhi[base + 8 * SPAD];
                ahi[mf][2] = *(const uint*)&sAhi[base + 8];
                ahi[mf][3] = *(const uint*)&sAhi[base + 8 * SPAD + 8];
                alo[mf][0] = *(const uint*)&sAlo[base];
                alo[mf][1] = *(const uint*)&sAlo[base + 8 * SPAD];
                alo[mf][2] = *(const uint*)&sAlo[base + 8];
                alo[mf][3] = *(const uint*)&sAlo[base + 8 * SPAD + 8];
            }
            uint bhi[4][2], blo[4][2];
#pragma unroll
            for (int nf = 0; nf < 4; ++nf) {
                int n = wn * 32 + nf * 8 + gid;
                int base = n * SPAD + kb;
                bhi[nf][0] = *(const uint*)&sWhi[base];
                bhi[nf][1] = *(const uint*)&sWhi[base + 8];
                blo[nf][0] = *(const uint*)&sWlo[base];
                blo[nf][1] = *(const uint*)&sWlo[base + 8];
            }
#pragma unroll
            for (int mf = 0; mf < 2; ++mf)
#pragma unroll
                for (int nf = 0; nf < 4; ++nf) {
                    mma16816(acc[mf][nf], ahi[mf], bhi[nf]);
                    mma16816(acc[mf][nf], ahi[mf], blo[nf]);
                    mma16816(acc[mf][nf], alo[mf], bhi[nf]);
                }
        }
    }

    // ---------- fused LSTM cell epilogue ----------
    const float* cprev = g_c[rpar] + (size_t)l * BH;
    float* cnew = g_c[wpar] + (size_t)l * BH;
    __nv_bfloat16* hhi = g_ahi + (size_t)(wpar * 3 + l) * BH;
    __nv_bfloat16* hlo = g_alo + (size_t)(wpar * 3 + l) * BH;

#pragma unroll
    for (int mf = 0; mf < 2; ++mf)
#pragma unroll
        for (int nf = 0; nf < 4; ++nf) {
            float d0 = acc[mf][nf][0], d1 = acc[mf][nf][1];
            float d2 = acc[mf][nf][2], d3 = acc[mf][nf][3];
            int cb = wn * 32 + nf * 8 + tg * 2;
            float b0 = g_bcomb[l * 2048 + nbase + cb];
            float b1 = g_bcomb[l * 2048 + nbase + cb + 1];
            d0 += b0; d1 += b1; d2 += b0; d3 += b1;
            float p0 = __shfl_xor_sync(0xffffffffu, d0, 1);
            float p1 = __shfl_xor_sync(0xffffffffu, d1, 1);
            float p2 = __shfl_xor_sync(0xffffffffu, d2, 1);
            float p3 = __shfl_xor_sync(0xffffffffu, d3, 1);
            // even tg lane: owns (i,f), partner has (g,o); computes row r.
            // odd  tg lane: owns (g,o), partner has (i,f); computes row r+8.
            int r = rbase + wm * 32 + mf * 16 + gid + ((tg & 1) ? 8 : 0);
            float I, F, G, O;
            if ((tg & 1) == 0) { I = d0; F = d1; G = p0; O = p1; }
            else               { I = p2; F = p3; G = d2; O = d3; }
            int j = jt * 16 + (cb >> 2);
            float Is = sigf(I), Fs = sigf(F), Gt = tanhf(G), Os = sigf(O);
            float cp = cprev[(size_t)r * 512 + j];
            float cn = Fs * cp + Is * Gt;
            float hn = Os * tanhf(cn);
            cnew[(size_t)r * 512 + j] = cn;
            __nv_bfloat16 hi = __float2bfloat16(hn);
            hhi[(size_t)r * 512 + j] = hi;
            hlo[(size_t)r * 512 + j] = __float2bfloat16(hn - __bfloat162float(hi));
            if (l == 2) g_res[((size_t)r * TSTEPS + t) * 512 + j] = hn;
        }
}

// ---------------- host launcher ----------------
extern "C" void kernel_launch(void* const* d_in, const int* in_sizes, int n_in,
                              void* d_out, int out_size)
{
    (void)in_sizes; (void)n_in; (void)out_size;
    const float* feat  = (const float*)d_in[0];
    const float* vw    = (const float*)d_in[1];
    const float* vb    = (const float*)d_in[2];
    const float* embed = (const float*)d_in[3];
    const float* w_ih  = (const float*)d_in[4];
    const float* w_hh  = (const float*)d_in[5];
    const float* b_ih  = (const float*)d_in[6];
    const float* b_hh  = (const float*)d_in[7];
    const float* pw1   = (const float*)d_in[8];
    const float* pb1   = (const float*)d_in[9];
    const float* pw2   = (const float*)d_in[10];
    const float* pb2   = (const float*)d_in[11];
    const int*   sidx  = (const int*)d_in[12];
    float* out = (float*)d_out;

    float *s_feat1, *s_h0, *s_res, *s_hmid;
    cudaGetSymbolAddress((void**)&s_feat1, g_feat1);
    cudaGetSymbolAddress((void**)&s_h0, g_h0);
    cudaGetSymbolAddress((void**)&s_res, g_res);
    cudaGetSymbolAddress((void**)&s_hmid, g_hmid);

    // 1) split weights to bf16 hi/lo, combine biases, split embed, zero c
    k_prep<<<512, 256>>>(w_ih, w_hh, b_ih, b_hh, embed, sidx);
    // 2) feat1 = feat @ Vw^T + vb
    k_gemm64<0><<<dim3(8, 4), 256>>>(feat, 512, vw, 512, vb, s_feat1, 512, 512);
    // 3) h0 = feat1 @ Vw^T + vb
    k_gemm64<0><<<dim3(8, 4), 256>>>(s_feat1, 512, vw, 512, vb, s_h0, 512, 512);
    // 4) split h0 into activation buffer 1 (all 3 layers)
    k_split0<<<256, 256>>>();
    // 5) 600 recurrent tensor-core iterations (stream order = sync)
    for (int t = 0; t < TSTEPS; ++t)
        for (int l = 0; l < LLAYERS; ++l)
            k_step<<<128, 128>>>(t, l);
    // 6) hmid = gelu(res @ W1^T + b1)
    k_gemm64<1><<<dim3(16, 800), 256>>>(s_res, 512, pw1, 512, pb1, s_hmid, 1024, 512);
    // 7) logits -> out[b][v][t]
    k_proj2<<<dim3(2, 800), 256>>>(s_hmid, pw2, pb2, out);
}

// round 9
// speedup vs baseline: 2.0485x; 1.0282x over previous
#include <cuda_runtime.h>
#include <cuda_bf16.h>
#include <math.h>

// Problem constants
#define BB 256
#define HH 512
#define LLAYERS 3
#define TSTEPS 200
#define VV 100
#define BH (256 * 512)

typedef unsigned long long ull;
typedef unsigned int uint;

// ---------------- device scratch (no allocations allowed) ----------------
__device__ __align__(16) __nv_bfloat16 g_whi[3u * 2048u * 1024u];  // weights hi, [l][(jj*4+gate)][k(x||h)]
__device__ __align__(16) __nv_bfloat16 g_wlo[3u * 2048u * 1024u];  // weights lo
__device__ __align__(16) float g_bcomb[3 * 2048];                  // b_ih + b_hh, gate-interleaved
__device__ __align__(16) __nv_bfloat16 g_ahi[2 * 3 * BH];          // activations hi (double-buffered)
__device__ __align__(16) __nv_bfloat16 g_alo[2 * 3 * BH];          // activations lo
__device__ __align__(16) __nv_bfloat16 g_ehi[512];                 // split embed <sos> row
__device__ __align__(16) __nv_bfloat16 g_elo[512];
__device__ __align__(16) float g_c[2][3 * BH];                     // cell states fp32
__device__ __align__(16) float g_feat1[BB * HH];
__device__ __align__(16) float g_h0[BB * HH];
__device__ __align__(16) float g_res[256u * 200u * 512u];          // [b][t][h]
__device__ __align__(16) float g_hmid[51200u * 1024u];

// ---------------- helpers ----------------
__device__ __forceinline__ ull pk2(float a, float b) {
    ull r; asm("mov.b64 %0, {%1, %2};" : "=l"(r) : "f"(a), "f"(b)); return r;
}
__device__ __forceinline__ float2 upk2(ull v) {
    float2 r; asm("mov.b64 {%0, %1}, %2;" : "=f"(r.x), "=f"(r.y) : "l"(v)); return r;
}
__device__ __forceinline__ void fma2(ull& d, ull a, ull b) {
    asm("fma.rn.f32x2 %0, %1, %2, %0;" : "+l"(d) : "l"(a), "l"(b));
}
__device__ __forceinline__ float sigf(float x) { return 1.0f / (1.0f + expf(-x)); }
__device__ __forceinline__ float geluf(float x) { return 0.5f * x * (1.0f + erff(x * 0.70710678118654752f)); }

__device__ __forceinline__ void mma16816(float d[4], const uint a[4], const uint b[2]) {
    asm volatile(
        "mma.sync.aligned.m16n8k16.row.col.f32.bf16.bf16.f32 "
        "{%0,%1,%2,%3}, {%4,%5,%6,%7}, {%8,%9}, {%0,%1,%2,%3};"
        : "+f"(d[0]), "+f"(d[1]), "+f"(d[2]), "+f"(d[3])
        : "r"(a[0]), "r"(a[1]), "r"(a[2]), "r"(a[3]), "r"(b[0]), "r"(b[1]));
}

// ================= fp32 path (init + projection) =================
template<bool GUARDB>
__device__ __forceinline__ void gemm_acc(ull acc[2][4],
                                         const float* __restrict__ A, int lda,
                                         const float* __restrict__ B, int ldb,
                                         int K, int rbase, int nbase, int nlimit,
                                         float* smem)
{
    float* As = smem;
    float* Bs = smem + 32 * 64;
    const int tid = threadIdx.x;
    const int tx = tid & 15, ty = tid >> 4;
    const int nchunks = K >> 5;

    float4 pa[2], pb[2];
#pragma unroll
    for (int i = 0; i < 2; ++i) {
        int idx = i * 256 + tid;
        int row = idx >> 3, kg = idx & 7;
        pa[i] = *(const float4*)(A + (size_t)(rbase + row) * lda + kg * 4);
        int n = nbase + row;
        if (GUARDB && n >= nlimit) pb[i] = make_float4(0.f, 0.f, 0.f, 0.f);
        else                       pb[i] = *(const float4*)(B + (size_t)n * ldb + kg * 4);
    }

    for (int kc = 0; kc < nchunks; ++kc) {
        __syncthreads();
#pragma unroll
        for (int i = 0; i < 2; ++i) {
            int idx = i * 256 + tid;
            int row = idx >> 3, kg = idx & 7;
            As[(kg * 4 + 0) * 64 + row] = pa[i].x;
            As[(kg * 4 + 1) * 64 + row] = pa[i].y;
            As[(kg * 4 + 2) * 64 + row] = pa[i].z;
            As[(kg * 4 + 3) * 64 + row] = pa[i].w;
            Bs[(kg * 4 + 0) * 64 + row] = pb[i].x;
            Bs[(kg * 4 + 1) * 64 + row] = pb[i].y;
            Bs[(kg * 4 + 2) * 64 + row] = pb[i].z;
            Bs[(kg * 4 + 3) * 64 + row] = pb[i].w;
        }
        __syncthreads();

        if (kc + 1 < nchunks) {
            int k0 = (kc + 1) * 32;
#pragma unroll
            for (int i = 0; i < 2; ++i) {
                int idx = i * 256 + tid;
                int row = idx >> 3, kg = idx & 7;
                pa[i] = *(const float4*)(A + (size_t)(rbase + row) * lda + k0 + kg * 4);
                int n = nbase + row;
                if (GUARDB && n >= nlimit) pb[i] = make_float4(0.f, 0.f, 0.f, 0.f);
                else                       pb[i] = *(const float4*)(B + (size_t)n * ldb + k0 + kg * 4);
            }
        }

#pragma unroll
        for (int k = 0; k < 32; ++k) {
            ull a0 = *(const ull*)&As[k * 64 + ty * 4 + 0];
            ull a1 = *(const ull*)&As[k * 64 + ty * 4 + 2];
            float4 wv = *(const float4*)&Bs[k * 64 + tx * 4];
            ull w0 = pk2(wv.x, wv.x), w1 = pk2(wv.y, wv.y);
            ull w2 = pk2(wv.z, wv.z), w3 = pk2(wv.w, wv.w);
            fma2(acc[0][0], a0, w0); fma2(acc[0][1], a0, w1); fma2(acc[0][2], a0, w2); fma2(acc[0][3], a0, w3);
            fma2(acc[1][0], a1, w0); fma2(acc[1][1], a1, w1); fma2(acc[1][2], a1, w2); fma2(acc[1][3], a1, w3);
        }
    }
    __syncthreads();
}

template<int EPI>
__global__ __launch_bounds__(256) void k_gemm64(const float* __restrict__ A, int lda,
                                                const float* __restrict__ B, int ldb,
                                                const float* __restrict__ bias,
                                                float* __restrict__ C, int ldc, int K)
{
    __shared__ float smem[2 * 32 * 64];
    ull acc[2][4] = {};
    const int rbase = blockIdx.y * 64;
    const int nbase = blockIdx.x * 64;
    gemm_acc<false>(acc, A, lda, B, ldb, K, rbase, nbase, 1 << 30, smem);

    const int tx = threadIdx.x & 15, ty = threadIdx.x >> 4;
#pragma unroll
    for (int p = 0; p < 2; ++p) {
        int r = rbase + ty * 4 + 2 * p;
#pragma unroll
        for (int c = 0; c < 4; ++c) {
            int n = nbase + tx * 4 + c;
            float2 v = upk2(acc[p][c]);
            float bz = bias[n];
            float x0 = v.x + bz, x1 = v.y + bz;
            if (EPI == 1) { x0 = geluf(x0); x1 = geluf(x1); }
            C[(size_t)r * ldc + n]       = x0;
            C[(size_t)(r + 1) * ldc + n] = x1;
        }
    }
}

__global__ __launch_bounds__(256) void k_proj2(const float* __restrict__ A,
                                               const float* __restrict__ W2,
                                               const float* __restrict__ b2,
                                               float* __restrict__ out)
{
    __shared__ float smem[2 * 32 * 64];
    ull acc[2][4] = {};
    const int rbase = blockIdx.y * 64;
    const int nbase = blockIdx.x * 64;
    gemm_acc<true>(acc, A, 1024, W2, 1024, 1024, rbase, nbase, VV, smem);

    const int tx = threadIdx.x & 15, ty = threadIdx.x >> 4;
#pragma unroll
    for (int p = 0; p < 2; ++p) {
        int r0 = rbase + ty * 4 + 2 * p;
#pragma unroll
        for (int c = 0; c < 4; ++c) {
            int v = nbase + tx * 4 + c;
            if (v >= VV) continue;
            float2 val = upk2(acc[p][c]);
            float bz = b2[v];
#pragma unroll
            for (int q = 0; q < 2; ++q) {
                int r = r0 + q;
                int b = r / TSTEPS, t = r - b * TSTEPS;
                out[((size_t)b * VV + v) * TSTEPS + t] = (q ? val.y : val.x) + bz;
            }
        }
    }
}

// ---------------- prep: split weights to bf16 hi/lo, biases, embed, zero c ----------------
__global__ void k_prep(const float* __restrict__ w_ih, const float* __restrict__ w_hh,
                       const float* __restrict__ b_ih, const float* __restrict__ b_hh,
                       const float* __restrict__ embed, const int* __restrict__ sidx)
{
    const size_t stride = (size_t)gridDim.x * blockDim.x;
    const size_t tid = (size_t)blockIdx.x * blockDim.x + threadIdx.x;
    const size_t nel = (size_t)3 * 2048 * 1024;
    for (size_t i = tid; i < nel; i += stride) {
        int k  = (int)(i & 1023);
        size_t np = i >> 10;
        int l  = (int)(np >> 11);
        int n2 = (int)(np & 2047);
        int jj = n2 >> 2, g = n2 & 3;
        int n  = g * 512 + jj;
        float w = (k < 512) ? w_ih[((size_t)l * 2048 + n) * 512 + k]
                            : w_hh[((size_t)l * 2048 + n) * 512 + (k - 512)];
        __nv_bfloat16 hi = __float2bfloat16(w);
        g_whi[i] = hi;
        g_wlo[i] = __float2bfloat16(w - __bfloat162float(hi));
    }
    for (size_t i = tid; i < 3 * 2048; i += stride) {
        int l = (int)(i >> 11), n2 = (int)(i & 2047);
        int jj = n2 >> 2, g = n2 & 3;
        int n = g * 512 + jj;
        g_bcomb[i] = b_ih[(size_t)l * 2048 + n] + b_hh[(size_t)l * 2048 + n];
    }
    for (size_t i = tid; i < 512; i += stride) {
        float e = embed[(size_t)(*sidx) * 512 + i];
        __nv_bfloat16 hi = __float2bfloat16(e);
        g_ehi[i] = hi;
        g_elo[i] = __float2bfloat16(e - __bfloat162float(hi));
    }
    for (size_t i = tid; i < (size_t)3 * BH; i += stride) g_c[1][i] = 0.f;
}

// split h0 fp32 -> hi/lo for all 3 layers of activation buffer 1
__global__ void k_split0()
{
    const int stride = gridDim.x * blockDim.x;
    for (int i = blockIdx.x * blockDim.x + threadIdx.x; i < BH; i += stride) {
        float v = g_h0[i];
        __nv_bfloat16 hi = __float2bfloat16(v);
        __nv_bfloat16 lo = __float2bfloat16(v - __bfloat162float(hi));
#pragma unroll
        for (int l = 0; l < 3; ++l) {
            g_ahi[(3 + l) * BH + i] = hi;
            g_alo[(3 + l) * BH + i] = lo;
        }
    }
}

// ---------------- recurrent step: bf16 split-product mma.sync GEMM + fused cell ----
// CTA tile M=64 x N=64, K=1024 (x||h).  256 threads = 8 warps (4M x 2N),
// warp tile 16x32 = 1 m16-frag x 4 n8-frags, mma.m16n8k16.
// 2 warps/SMSP -> 16 independent HMMA chains per scheduler (latency hiding).
// SMEM rows padded to 72 bf16 -> fragment LDS conflict-free.
#define SPAD 72
__global__ __launch_bounds__(256) void k_step(int t, int l)
{
    __shared__ __nv_bfloat16 sAhi[64 * SPAD];
    __shared__ __nv_bfloat16 sAlo[64 * SPAD];
    __shared__ __nv_bfloat16 sWhi[64 * SPAD];
    __shared__ __nv_bfloat16 sWlo[64 * SPAD];

    const int tid = threadIdx.x;
    const int wid = tid >> 5, lane = tid & 31;
    const int gid = lane >> 2, tg = lane & 3;
    const int wm = wid >> 1, wn = wid & 1;       // 4 M-tiles x 2 N-tiles
    const int mt = blockIdx.x >> 5, jt = blockIdx.x & 31;
    const int rbase = mt * 64, nbase = jt * 64;
    const int wpar = t & 1, rpar = wpar ^ 1;

    // weight rows for this CTA
    const __nv_bfloat16* Whi = g_whi + ((size_t)l * 2048 + nbase) * 1024;
    const __nv_bfloat16* Wlo = g_wlo + ((size_t)l * 2048 + nbase) * 1024;

    // A sources: x-part (k 0..511) and h-part (k 512..1023)
    const __nv_bfloat16 *Axh, *Axl; int ldax;
    if (l == 0) {
        if (t == 0) { Axh = g_ehi; Axl = g_elo; ldax = 0; }
        else        { Axh = g_ahi + (size_t)(rpar * 3 + 2) * BH + (size_t)rbase * 512;
                      Axl = g_alo + (size_t)(rpar * 3 + 2) * BH + (size_t)rbase * 512; ldax = 512; }
    } else {
        Axh = g_ahi + (size_t)(wpar * 3 + l - 1) * BH + (size_t)rbase * 512;
        Axl = g_alo + (size_t)(wpar * 3 + l - 1) * BH + (size_t)rbase * 512; ldax = 512;
    }
    const __nv_bfloat16* Ahh = g_ahi + (size_t)(rpar * 3 + l) * BH + (size_t)rbase * 512;
    const __nv_bfloat16* All = g_alo + (size_t)(rpar * 3 + l) * BH + (size_t)rbase * 512;

    float acc[4][4] = {};     // 4 n8-frags x 4 f32

    uint4 pah[2], pal[2], pwh[2], pwl[2];
    // prefetch chunk 0 (A: x-part).  512 uint4 per array / 256 threads = 2 each.
#pragma unroll
    for (int i = 0; i < 2; ++i) {
        int idx = i * 256 + tid;
        int row = idx >> 3, kg = idx & 7;
        int ke = kg * 8;
        pah[i] = *(const uint4*)(Axh + (size_t)row * ldax + ke);
        pal[i] = *(const uint4*)(Axl + (size_t)row * ldax + ke);
        pwh[i] = *(const uint4*)(Whi + (size_t)row * 1024 + ke);
        pwl[i] = *(const uint4*)(Wlo + (size_t)row * 1024 + ke);
    }

    for (int kc = 0; kc < 16; ++kc) {
        __syncthreads();
#pragma unroll
        for (int i = 0; i < 2; ++i) {
            int idx = i * 256 + tid;
            int row = idx >> 3, kg = idx & 7;
            int so = row * SPAD + kg * 8;
            *(uint4*)&sAhi[so] = pah[i];
            *(uint4*)&sAlo[so] = pal[i];
            *(uint4*)&sWhi[so] = pwh[i];
            *(uint4*)&sWlo[so] = pwl[i];
        }
        __syncthreads();

        if (kc + 1 < 16) {
            int kn = kc + 1;
            const __nv_bfloat16 *Ah, *Al; int lda_, koff;
            if (kn < 8) { Ah = Axh; Al = Axl; lda_ = ldax; koff = kn * 64; }
            else        { Ah = Ahh; Al = All; lda_ = 512;  koff = kn * 64 - 512; }
            int kW = kn * 64;
#pragma unroll
            for (int i = 0; i < 2; ++i) {
                int idx = i * 256 + tid;
                int row = idx >> 3, kg = idx & 7;
                int ke = kg * 8;
                pah[i] = *(const uint4*)(Ah + (size_t)row * lda_ + koff + ke);
                pal[i] = *(const uint4*)(Al + (size_t)row * lda_ + koff + ke);
                pwh[i] = *(const uint4*)(Whi + (size_t)row * 1024 + kW + ke);
                pwl[i] = *(const uint4*)(Wlo + (size_t)row * 1024 + kW + ke);
            }
        }

#pragma unroll
        for (int k4 = 0; k4 < 4; ++k4) {
            int kb = k4 * 16 + tg * 2;
            uint ahi[4], alo[4];
            {
                int r = wm * 16 + gid;
                int base = r * SPAD + kb;
                ahi[0] = *(const uint*)&sAhi[base];
                ahi[1] = *(const uint*)&sAhi[base + 8 * SPAD];
                ahi[2] = *(const uint*)&sAhi[base + 8];
                ahi[3] = *(const uint*)&sAhi[base + 8 * SPAD + 8];
                alo[0] = *(const uint*)&sAlo[base];
                alo[1] = *(const uint*)&sAlo[base + 8 * SPAD];
                alo[2] = *(const uint*)&sAlo[base + 8];
                alo[3] = *(const uint*)&sAlo[base + 8 * SPAD + 8];
            }
            uint bhi[4][2], blo[4][2];
#pragma unroll
            for (int nf = 0; nf < 4; ++nf) {
                int n = wn * 32 + nf * 8 + gid;
                int base = n * SPAD + kb;
                bhi[nf][0] = *(const uint*)&sWhi[base];
                bhi[nf][1] = *(const uint*)&sWhi[base + 8];
                blo[nf][0] = *(const uint*)&sWlo[base];
                blo[nf][1] = *(const uint*)&sWlo[base + 8];
            }
#pragma unroll
            for (int nf = 0; nf < 4; ++nf) {
                mma16816(acc[nf], ahi, bhi[nf]);
                mma16816(acc[nf], ahi, blo[nf]);
                mma16816(acc[nf], alo, bhi[nf]);
            }
        }
    }

    // ---------- fused LSTM cell epilogue ----------
    const float* cprev = g_c[rpar] + (size_t)l * BH;
    float* cnew = g_c[wpar] + (size_t)l * BH;
    __nv_bfloat16* hhi = g_ahi + (size_t)(wpar * 3 + l) * BH;
    __nv_bfloat16* hlo = g_alo + (size_t)(wpar * 3 + l) * BH;

#pragma unroll
    for (int nf = 0; nf < 4; ++nf) {
        float d0 = acc[nf][0], d1 = acc[nf][1];
        float d2 = acc[nf][2], d3 = acc[nf][3];
        int cb = wn * 32 + nf * 8 + tg * 2;
        float b0 = g_bcomb[l * 2048 + nbase + cb];
        float b1 = g_bcomb[l * 2048 + nbase + cb + 1];
        d0 += b0; d1 += b1; d2 += b0; d3 += b1;
        float p0 = __shfl_xor_sync(0xffffffffu, d0, 1);
        float p1 = __shfl_xor_sync(0xffffffffu, d1, 1);
        float p2 = __shfl_xor_sync(0xffffffffu, d2, 1);
        float p3 = __shfl_xor_sync(0xffffffffu, d3, 1);
        // even tg lane: owns (i,f), partner has (g,o); computes row r.
        // odd  tg lane: owns (g,o), partner has (i,f); computes row r+8.
        int r = rbase + wm * 16 + gid + ((tg & 1) ? 8 : 0);
        float I, F, G, O;
        if ((tg & 1) == 0) { I = d0; F = d1; G = p0; O = p1; }
        else               { I = p2; F = p3; G = d2; O = d3; }
        int j = jt * 16 + (cb >> 2);
        float Is = sigf(I), Fs = sigf(F), Gt = tanhf(G), Os = sigf(O);
        float cp = cprev[(size_t)r * 512 + j];
        float cn = Fs * cp + Is * Gt;
        float hn = Os * tanhf(cn);
        cnew[(size_t)r * 512 + j] = cn;
        __nv_bfloat16 hi = __float2bfloat16(hn);
        hhi[(size_t)r * 512 + j] = hi;
        hlo[(size_t)r * 512 + j] = __float2bfloat16(hn - __bfloat162float(hi));
        if (l == 2) g_res[((size_t)r * TSTEPS + t) * 512 + j] = hn;
    }
}

// ---------------- host launcher ----------------
extern "C" void kernel_launch(void* const* d_in, const int* in_sizes, int n_in,
                              void* d_out, int out_size)
{
    (void)in_sizes; (void)n_in; (void)out_size;
    const float* feat  = (const float*)d_in[0];
    const float* vw    = (const float*)d_in[1];
    const float* vb    = (const float*)d_in[2];
    const float* embed = (const float*)d_in[3];
    const float* w_ih  = (const float*)d_in[4];
    const float* w_hh  = (const float*)d_in[5];
    const float* b_ih  = (const float*)d_in[6];
    const float* b_hh  = (const float*)d_in[7];
    const float* pw1   = (const float*)d_in[8];
    const float* pb1   = (const float*)d_in[9];
    const float* pw2   = (const float*)d_in[10];
    const float* pb2   = (const float*)d_in[11];
    const int*   sidx  = (const int*)d_in[12];
    float* out = (float*)d_out;

    float *s_feat1, *s_h0, *s_res, *s_hmid;
    cudaGetSymbolAddress((void**)&s_feat1, g_feat1);
    cudaGetSymbolAddress((void**)&s_h0, g_h0);
    cudaGetSymbolAddress((void**)&s_res, g_res);
    cudaGetSymbolAddress((void**)&s_hmid, g_hmid);

    // 1) split weights to bf16 hi/lo, combine biases, split embed, zero c
    k_prep<<<512, 256>>>(w_ih, w_hh, b_ih, b_hh, embed, sidx);
    // 2) feat1 = feat @ Vw^T + vb
    k_gemm64<0><<<dim3(8, 4), 256>>>(feat, 512, vw, 512, vb, s_feat1, 512, 512);
    // 3) h0 = feat1 @ Vw^T + vb
    k_gemm64<0><<<dim3(8, 4), 256>>>(s_feat1, 512, vw, 512, vb, s_h0, 512, 512);
    // 4) split h0 into activation buffer 1 (all 3 layers)
    k_split0<<<256, 256>>>();
    // 5) 600 recurrent tensor-core iterations (stream order = sync)
    for (int t = 0; t < TSTEPS; ++t)
        for (int l = 0; l < LLAYERS; ++l)
            k_step<<<128, 256>>>(t, l);
    // 6) hmid = gelu(res @ W1^T + b1)
    k_gemm64<1><<<dim3(16, 800), 256>>>(s_res, 512, pw1, 512, pb1, s_hmid, 1024, 512);
    // 7) logits -> out[b][v][t]
    k_proj2<<<dim3(2, 800), 256>>>(s_hmid, pw2, pb2, out);
}

// round 10
// speedup vs baseline: 2.6017x; 1.2701x over previous
#include <cuda_runtime.h>
#include <cuda_fp16.h>
#include <math.h>

// Problem constants
#define BB 256
#define HH 512
#define LLAYERS 3
#define TSTEPS 200
#define VV 100
#define BH (256 * 512)

typedef unsigned long long ull;
typedef unsigned int uint;

// ---------------- device scratch (no allocations allowed) ----------------
__device__ __align__(16) __half g_whi[3u * 2048u * 1024u];  // weights hi fp16, [l][(jj*4+gate)][k(x||h)]
__device__ __align__(16) __half g_wlo[3u * 2048u * 1024u];  // weights lo fp16, pre-scaled x4096
__device__ __align__(16) float g_bcomb[3 * 2048];           // b_ih + b_hh, gate-interleaved
__device__ __align__(16) __half g_a[2 * 3 * BH];            // activations fp16 (double-buffered [buf*3+l])
__device__ __align__(16) __half g_e[512];                   // embed <sos> row fp16
__device__ __align__(16) float g_c[2][3 * BH];              // cell states fp32
__device__ __align__(16) float g_feat1[BB * HH];
__device__ __align__(16) float g_h0[BB * HH];
__device__ __align__(16) float g_res[256u * 200u * 512u];   // [b][t][h]
__device__ __align__(16) float g_hmid[51200u * 1024u];

// ---------------- helpers ----------------
__device__ __forceinline__ ull pk2(float a, float b) {
    ull r; asm("mov.b64 %0, {%1, %2};" : "=l"(r) : "f"(a), "f"(b)); return r;
}
__device__ __forceinline__ float2 upk2(ull v) {
    float2 r; asm("mov.b64 {%0, %1}, %2;" : "=f"(r.x), "=f"(r.y) : "l"(v)); return r;
}
__device__ __forceinline__ void fma2(ull& d, ull a, ull b) {
    asm("fma.rn.f32x2 %0, %1, %2, %0;" : "+l"(d) : "l"(a), "l"(b));
}
__device__ __forceinline__ float sigf(float x) { return 1.0f / (1.0f + expf(-x)); }
__device__ __forceinline__ float geluf(float x) { return 0.5f * x * (1.0f + erff(x * 0.70710678118654752f)); }

__device__ __forceinline__ void mma16816h(float d[4], const uint a[4], const uint b[2]) {
    asm volatile(
        "mma.sync.aligned.m16n8k16.row.col.f32.f16.f16.f32 "
        "{%0,%1,%2,%3}, {%4,%5,%6,%7}, {%8,%9}, {%0,%1,%2,%3};"
        : "+f"(d[0]), "+f"(d[1]), "+f"(d[2]), "+f"(d[3])
        : "r"(a[0]), "r"(a[1]), "r"(a[2]), "r"(a[3]), "r"(b[0]), "r"(b[1]));
}

// ================= fp32 path (init + projection) =================
template<bool GUARDB>
__device__ __forceinline__ void gemm_acc(ull acc[2][4],
                                         const float* __restrict__ A, int lda,
                                         const float* __restrict__ B, int ldb,
                                         int K, int rbase, int nbase, int nlimit,
                                         float* smem)
{
    float* As = smem;
    float* Bs = smem + 32 * 64;
    const int tid = threadIdx.x;
    const int tx = tid & 15, ty = tid >> 4;
    const int nchunks = K >> 5;

    float4 pa[2], pb[2];
#pragma unroll
    for (int i = 0; i < 2; ++i) {
        int idx = i * 256 + tid;
        int row = idx >> 3, kg = idx & 7;
        pa[i] = *(const float4*)(A + (size_t)(rbase + row) * lda + kg * 4);
        int n = nbase + row;
        if (GUARDB && n >= nlimit) pb[i] = make_float4(0.f, 0.f, 0.f, 0.f);
        else                       pb[i] = *(const float4*)(B + (size_t)n * ldb + kg * 4);
    }

    for (int kc = 0; kc < nchunks; ++kc) {
        __syncthreads();
#pragma unroll
        for (int i = 0; i < 2; ++i) {
            int idx = i * 256 + tid;
            int row = idx >> 3, kg = idx & 7;
            As[(kg * 4 + 0) * 64 + row] = pa[i].x;
            As[(kg * 4 + 1) * 64 + row] = pa[i].y;
            As[(kg * 4 + 2) * 64 + row] = pa[i].z;
            As[(kg * 4 + 3) * 64 + row] = pa[i].w;
            Bs[(kg * 4 + 0) * 64 + row] = pb[i].x;
            Bs[(kg * 4 + 1) * 64 + row] = pb[i].y;
            Bs[(kg * 4 + 2) * 64 + row] = pb[i].z;
            Bs[(kg * 4 + 3) * 64 + row] = pb[i].w;
        }
        __syncthreads();

        if (kc + 1 < nchunks) {
            int k0 = (kc + 1) * 32;
#pragma unroll
            for (int i = 0; i < 2; ++i) {
                int idx = i * 256 + tid;
                int row = idx >> 3, kg = idx & 7;
                pa[i] = *(const float4*)(A + (size_t)(rbase + row) * lda + k0 + kg * 4);
                int n = nbase + row;
                if (GUARDB && n >= nlimit) pb[i] = make_float4(0.f, 0.f, 0.f, 0.f);
                else                       pb[i] = *(const float4*)(B + (size_t)n * ldb + k0 + kg * 4);
            }
        }

#pragma unroll
        for (int k = 0; k < 32; ++k) {
            ull a0 = *(const ull*)&As[k * 64 + ty * 4 + 0];
            ull a1 = *(const ull*)&As[k * 64 + ty * 4 + 2];
            float4 wv = *(const float4*)&Bs[k * 64 + tx * 4];
            ull w0 = pk2(wv.x, wv.x), w1 = pk2(wv.y, wv.y);
            ull w2 = pk2(wv.z, wv.z), w3 = pk2(wv.w, wv.w);
            fma2(acc[0][0], a0, w0); fma2(acc[0][1], a0, w1); fma2(acc[0][2], a0, w2); fma2(acc[0][3], a0, w3);
            fma2(acc[1][0], a1, w0); fma2(acc[1][1], a1, w1); fma2(acc[1][2], a1, w2); fma2(acc[1][3], a1, w3);
        }
    }
    __syncthreads();
}

template<int EPI>
__global__ __launch_bounds__(256) void k_gemm64(const float* __restrict__ A, int lda,
                                                const float* __restrict__ B, int ldb,
                                                const float* __restrict__ bias,
                                                float* __restrict__ C, int ldc, int K)
{
    __shared__ float smem[2 * 32 * 64];
    ull acc[2][4] = {};
    const int rbase = blockIdx.y * 64;
    const int nbase = blockIdx.x * 64;
    gemm_acc<false>(acc, A, lda, B, ldb, K, rbase, nbase, 1 << 30, smem);

    const int tx = threadIdx.x & 15, ty = threadIdx.x >> 4;
#pragma unroll
    for (int p = 0; p < 2; ++p) {
        int r = rbase + ty * 4 + 2 * p;
#pragma unroll
        for (int c = 0; c < 4; ++c) {
            int n = nbase + tx * 4 + c;
            float2 v = upk2(acc[p][c]);
            float bz = bias[n];
            float x0 = v.x + bz, x1 = v.y + bz;
            if (EPI == 1) { x0 = geluf(x0); x1 = geluf(x1); }
            C[(size_t)r * ldc + n]       = x0;
            C[(size_t)(r + 1) * ldc + n] = x1;
        }
    }
}

__global__ __launch_bounds__(256) void k_proj2(const float* __restrict__ A,
                                               const float* __restrict__ W2,
                                               const float* __restrict__ b2,
                                               float* __restrict__ out)
{
    __shared__ float smem[2 * 32 * 64];
    ull acc[2][4] = {};
    const int rbase = blockIdx.y * 64;
    const int nbase = blockIdx.x * 64;
    gemm_acc<true>(acc, A, 1024, W2, 1024, 1024, rbase, nbase, VV, smem);

    const int tx = threadIdx.x & 15, ty = threadIdx.x >> 4;
#pragma unroll
    for (int p = 0; p < 2; ++p) {
        int r0 = rbase + ty * 4 + 2 * p;
#pragma unroll
        for (int c = 0; c < 4; ++c) {
            int v = nbase + tx * 4 + c;
            if (v >= VV) continue;
            float2 val = upk2(acc[p][c]);
            float bz = b2[v];
#pragma unroll
            for (int q = 0; q < 2; ++q) {
                int r = r0 + q;
                int b = r / TSTEPS, t = r - b * TSTEPS;
                out[((size_t)b * VV + v) * TSTEPS + t] = (q ? val.y : val.x) + bz;
            }
        }
    }
}

// ---------------- prep: split weights fp16 hi + scaled-lo, biases, embed, zero c ----------------
__global__ void k_prep(const float* __restrict__ w_ih, const float* __restrict__ w_hh,
                       const float* __restrict__ b_ih, const float* __restrict__ b_hh,
                       const float* __restrict__ embed, const int* __restrict__ sidx)
{
    const size_t stride = (size_t)gridDim.x * blockDim.x;
    const size_t tid = (size_t)blockIdx.x * blockDim.x + threadIdx.x;
    const size_t nel = (size_t)3 * 2048 * 1024;
    for (size_t i = tid; i < nel; i += stride) {
        int k  = (int)(i & 1023);
        size_t np = i >> 10;
        int l  = (int)(np >> 11);
        int n2 = (int)(np & 2047);
        int jj = n2 >> 2, g = n2 & 3;
        int n  = g * 512 + jj;
        float w = (k < 512) ? w_ih[((size_t)l * 2048 + n) * 512 + k]
                            : w_hh[((size_t)l * 2048 + n) * 512 + (k - 512)];
        __half hi = __float2half(w);
        g_whi[i] = hi;
        g_wlo[i] = __float2half(4096.0f * (w - __half2float(hi)));  // pre-scaled lo (normal range)
    }
    for (size_t i = tid; i < 3 * 2048; i += stride) {
        int l = (int)(i >> 11), n2 = (int)(i & 2047);
        int jj = n2 >> 2, g = n2 & 3;
        int n = g * 512 + jj;
        g_bcomb[i] = b_ih[(size_t)l * 2048 + n] + b_hh[(size_t)l * 2048 + n];
    }
    for (size_t i = tid; i < 512; i += stride)
        g_e[i] = __float2half(embed[(size_t)(*sidx) * 512 + i]);
    for (size_t i = tid; i < (size_t)3 * BH; i += stride) g_c[1][i] = 0.f;
}

// h0 fp32 -> fp16 for all 3 layers of activation buffer 1
__global__ void k_split0()
{
    const int stride = gridDim.x * blockDim.x;
    for (int i = blockIdx.x * blockDim.x + threadIdx.x; i < BH; i += stride) {
        __half v = __float2half(g_h0[i]);
#pragma unroll
        for (int l = 0; l < 3; ++l) g_a[(3 + l) * BH + i] = v;
    }
}

// ---------------- recurrent step: fp16 2-term weight-split mma GEMM + fused cell ----
// CTA tile M=64 x N=64, K=1024 (x||h).  256 threads = 8 warps (4M x 2N),
// warp tile 16x32 = 1 m16-frag x 4 n8-frags, mma.m16n8k16.f16.
// 2 terms: accA += a*whi, accB += a*wlo'(x4096); d = accA + 2^-12*accB.
// SMEM rows padded to 72 halves -> fragment LDS conflict-free.
#define SPAD 72
__global__ __launch_bounds__(256) void k_step(int t, int l)
{
    __shared__ __half sA  [64 * SPAD];
    __shared__ __half sWhi[64 * SPAD];
    __shared__ __half sWlo[64 * SPAD];

    const int tid = threadIdx.x;
    const int wid = tid >> 5, lane = tid & 31;
    const int gid = lane >> 2, tg = lane & 3;
    const int wm = wid >> 1, wn = wid & 1;       // 4 M-tiles x 2 N-tiles
    const int mt = blockIdx.x >> 5, jt = blockIdx.x & 31;
    const int rbase = mt * 64, nbase = jt * 64;
    const int wpar = t & 1, rpar = wpar ^ 1;

    // weight rows for this CTA
    const __half* Whi = g_whi + ((size_t)l * 2048 + nbase) * 1024;
    const __half* Wlo = g_wlo + ((size_t)l * 2048 + nbase) * 1024;

    // A sources: x-part (k 0..511) and h-part (k 512..1023)
    const __half* Ax; int ldax;
    if (l == 0) {
        if (t == 0) { Ax = g_e; ldax = 0; }
        else        { Ax = g_a + (size_t)(rpar * 3 + 2) * BH + (size_t)rbase * 512; ldax = 512; }
    } else {
        Ax = g_a + (size_t)(wpar * 3 + l - 1) * BH + (size_t)rbase * 512; ldax = 512;
    }
    const __half* Ahh = g_a + (size_t)(rpar * 3 + l) * BH + (size_t)rbase * 512;

    float accA[4][4] = {};    // a * whi
    float accB[4][4] = {};    // a * wlo'  (x4096)

    uint4 pa[2], pwh[2], pwl[2];
    // prefetch chunk 0 (A: x-part).  512 uint4 per array / 256 threads = 2 each.
#pragma unroll
    for (int i = 0; i < 2; ++i) {
        int idx = i * 256 + tid;
        int row = idx >> 3, kg = idx & 7;
        int ke = kg * 8;
        pa[i]  = *(const uint4*)(Ax  + (size_t)row * ldax + ke);
        pwh[i] = *(const uint4*)(Whi + (size_t)row * 1024 + ke);
        pwl[i] = *(const uint4*)(Wlo + (size_t)row * 1024 + ke);
    }

    for (int kc = 0; kc < 16; ++kc) {
        __syncthreads();
#pragma unroll
        for (int i = 0; i < 2; ++i) {
            int idx = i * 256 + tid;
            int row = idx >> 3, kg = idx & 7;
            int so = row * SPAD + kg * 8;
            *(uint4*)&sA[so]   = pa[i];
            *(uint4*)&sWhi[so] = pwh[i];
            *(uint4*)&sWlo[so] = pwl[i];
        }
        __syncthreads();

        if (kc + 1 < 16) {
            int kn = kc + 1;
            const __half* Ah; int lda_, koff;
            if (kn < 8) { Ah = Ax;  lda_ = ldax; koff = kn * 64; }
            else        { Ah = Ahh; lda_ = 512;  koff = kn * 64 - 512; }
            int kW = kn * 64;
#pragma unroll
            for (int i = 0; i < 2; ++i) {
                int idx = i * 256 + tid;
                int row = idx >> 3, kg = idx & 7;
                int ke = kg * 8;
                pa[i]  = *(const uint4*)(Ah  + (size_t)row * lda_ + koff + ke);
                pwh[i] = *(const uint4*)(Whi + (size_t)row * 1024 + kW + ke);
                pwl[i] = *(const uint4*)(Wlo + (size_t)row * 1024 + kW + ke);
            }
        }

#pragma unroll
        for (int k4 = 0; k4 < 4; ++k4) {
            int kb = k4 * 16 + tg * 2;
            uint a[4];
            {
                int r = wm * 16 + gid;
                int base = r * SPAD + kb;
                a[0] = *(const uint*)&sA[base];
                a[1] = *(const uint*)&sA[base + 8 * SPAD];
                a[2] = *(const uint*)&sA[base + 8];
                a[3] = *(const uint*)&sA[base + 8 * SPAD + 8];
            }
            uint bhi[4][2], blo[4][2];
#pragma unroll
            for (int nf = 0; nf < 4; ++nf) {
                int n = wn * 32 + nf * 8 + gid;
                int base = n * SPAD + kb;
                bhi[nf][0] = *(const uint*)&sWhi[base];
                bhi[nf][1] = *(const uint*)&sWhi[base + 8];
                blo[nf][0] = *(const uint*)&sWlo[base];
                blo[nf][1] = *(const uint*)&sWlo[base + 8];
            }
#pragma unroll
            for (int nf = 0; nf < 4; ++nf) {
                mma16816h(accA[nf], a, bhi[nf]);
                mma16816h(accB[nf], a, blo[nf]);
            }
        }
    }

    // ---------- fused LSTM cell epilogue ----------
    const float* cprev = g_c[rpar] + (size_t)l * BH;
    float* cnew = g_c[wpar] + (size_t)l * BH;
    __half* hout = g_a + (size_t)(wpar * 3 + l) * BH;
    const float LSC = 1.0f / 4096.0f;

#pragma unroll
    for (int nf = 0; nf < 4; ++nf) {
        float d0 = accA[nf][0] + LSC * accB[nf][0];
        float d1 = accA[nf][1] + LSC * accB[nf][1];
        float d2 = accA[nf][2] + LSC * accB[nf][2];
        float d3 = accA[nf][3] + LSC * accB[nf][3];
        int cb = wn * 32 + nf * 8 + tg * 2;
        float b0 = g_bcomb[l * 2048 + nbase + cb];
        float b1 = g_bcomb[l * 2048 + nbase + cb + 1];
        d0 += b0; d1 += b1; d2 += b0; d3 += b1;
        float p0 = __shfl_xor_sync(0xffffffffu, d0, 1);
        float p1 = __shfl_xor_sync(0xffffffffu, d1, 1);
        float p2 = __shfl_xor_sync(0xffffffffu, d2, 1);
        float p3 = __shfl_xor_sync(0xffffffffu, d3, 1);
        // even tg lane: owns (i,f), partner has (g,o); computes row r.
        // odd  tg lane: owns (g,o), partner has (i,f); computes row r+8.
        int r = rbase + wm * 16 + gid + ((tg & 1) ? 8 : 0);
        float I, F, G, O;
        if ((tg & 1) == 0) { I = d0; F = d1; G = p0; O = p1; }
        else               { I = p2; F = p3; G = d2; O = d3; }
        int j = jt * 16 + (cb >> 2);
        float Is = sigf(I), Fs = sigf(F), Gt = tanhf(G), Os = sigf(O);
        float cp = cprev[(size_t)r * 512 + j];
        float cn = Fs * cp + Is * Gt;
        float hn = Os * tanhf(cn);
        cnew[(size_t)r * 512 + j] = cn;
        hout[(size_t)r * 512 + j] = __float2half(hn);
        if (l == 2) g_res[((size_t)r * TSTEPS + t) * 512 + j] = hn;
    }
}

// ---------------- host launcher ----------------
extern "C" void kernel_launch(void* const* d_in, const int* in_sizes, int n_in,
                              void* d_out, int out_size)
{
    (void)in_sizes; (void)n_in; (void)out_size;
    const float* feat  = (const float*)d_in[0];
    const float* vw    = (const float*)d_in[1];
    const float* vb    = (const float*)d_in[2];
    const float* embed = (const float*)d_in[3];
    const float* w_ih  = (const float*)d_in[4];
    const float* w_hh  = (const float*)d_in[5];
    const float* b_ih  = (const float*)d_in[6];
    const float* b_hh  = (const float*)d_in[7];
    const float* pw1   = (const float*)d_in[8];
    const float* pb1   = (const float*)d_in[9];
    const float* pw2   = (const float*)d_in[10];
    const float* pb2   = (const float*)d_in[11];
    const int*   sidx  = (const int*)d_in[12];
    float* out = (float*)d_out;

    float *s_feat1, *s_h0, *s_res, *s_hmid;
    cudaGetSymbolAddress((void**)&s_feat1, g_feat1);
    cudaGetSymbolAddress((void**)&s_h0, g_h0);
    cudaGetSymbolAddress((void**)&s_res, g_res);
    cudaGetSymbolAddress((void**)&s_hmid, g_hmid);

    // 1) split weights fp16 hi + scaled-lo, combine biases, embed, zero c
    k_prep<<<512, 256>>>(w_ih, w_hh, b_ih, b_hh, embed, sidx);
    // 2) feat1 = feat @ Vw^T + vb
    k_gemm64<0><<<dim3(8, 4), 256>>>(feat, 512, vw, 512, vb, s_feat1, 512, 512);
    // 3) h0 = feat1 @ Vw^T + vb
    k_gemm64<0><<<dim3(8, 4), 256>>>(s_feat1, 512, vw, 512, vb, s_h0, 512, 512);
    // 4) h0 -> fp16 activation buffer 1 (all 3 layers)
    k_split0<<<256, 256>>>();
    // 5) 600 recurrent tensor-core iterations (stream order = sync)
    for (int t = 0; t < TSTEPS; ++t)
        for (int l = 0; l < LLAYERS; ++l)
            k_step<<<128, 256>>>(t, l);
    // 6) hmid = gelu(res @ W1^T + b1)
    k_gemm64<1><<<dim3(16, 800), 256>>>(s_res, 512, pw1, 512, pb1, s_hmid, 1024, 512);
    // 7) logits -> out[b][v][t]
    k_proj2<<<dim3(2, 800), 256>>>(s_hmid, pw2, pb2, out);
}

// round 12
// speedup vs baseline: 3.0398x; 1.1684x over previous
#include <cuda_runtime.h>
#include <cuda_fp16.h>
#include <math.h>

// Problem constants
#define BB 256
#define HH 512
#define LLAYERS 3
#define TSTEPS 200
#define VV 100
#define BH (256 * 512)

typedef unsigned long long ull;
typedef unsigned int uint;

// ---------------- device scratch (no allocations allowed) ----------------
__device__ __align__(16) __half g_whi[3u * 2048u * 1024u];  // LSTM weights hi fp16
__device__ __align__(16) __half g_wlo[3u * 2048u * 1024u];  // LSTM weights lo fp16 (x4096)
__device__ __align__(16) float g_bcomb[3 * 2048];           // b_ih + b_hh, gate-interleaved
__device__ __align__(16) __half g_a[2 * 3 * BH];            // activations fp16 (double-buffered)
__device__ __align__(16) __half g_e[512];                   // embed <sos> row fp16
__device__ __align__(16) float g_c[2][3 * BH];              // cell states fp32
__device__ __align__(16) float g_feat1[BB * HH];
__device__ __align__(16) float g_h0[BB * HH];
__device__ __align__(16) __half g_res16[256u * 200u * 512u];   // [b][t][h] fp16
__device__ __align__(16) __half g_hmid16[51200u * 1024u];      // fp16
__device__ __align__(16) __half g_p1hi[1024u * 512u];          // proj_w1 hi
__device__ __align__(16) __half g_p1lo[1024u * 512u];          // proj_w1 lo (x4096)
__device__ __align__(16) __half g_p2hi[128u * 1024u];          // proj_w2 hi, rows 100..127 zero
__device__ __align__(16) __half g_p2lo[128u * 1024u];          // proj_w2 lo (x4096), padded
__device__ __align__(16) float g_pb2[128];                     // b2 padded

// ---------------- helpers ----------------
__device__ __forceinline__ ull pk2(float a, float b) {
    ull r; asm("mov.b64 %0, {%1, %2};" : "=l"(r) : "f"(a), "f"(b)); return r;
}
__device__ __forceinline__ float2 upk2(ull v) {
    float2 r; asm("mov.b64 {%0, %1}, %2;" : "=f"(r.x), "=f"(r.y) : "l"(v)); return r;
}
__device__ __forceinline__ void fma2(ull& d, ull a, ull b) {
    asm("fma.rn.f32x2 %0, %1, %2, %0;" : "+l"(d) : "l"(a), "l"(b));
}
__device__ __forceinline__ float sigf(float x) { return 1.0f / (1.0f + expf(-x)); }
__device__ __forceinline__ float geluf(float x) { return 0.5f * x * (1.0f + erff(x * 0.70710678118654752f)); }

__device__ __forceinline__ void mma16816h(float d[4], const uint a[4], const uint b[2]) {
    asm volatile(
        "mma.sync.aligned.m16n8k16.row.col.f32.f16.f16.f32 "
        "{%0,%1,%2,%3}, {%4,%5,%6,%7}, {%8,%9}, {%0,%1,%2,%3};"
        : "+f"(d[0]), "+f"(d[1]), "+f"(d[2]), "+f"(d[3])
        : "r"(a[0]), "r"(a[1]), "r"(a[2]), "r"(a[3]), "r"(b[0]), "r"(b[1]));
}

#define SPAD 72
#define LSC (1.0f / 4096.0f)

// ---------------- generic fp16 2-term mainloop (64x64 tile, 256 thr, 8 warps) ----
// accA += A*Whi, accB += A*Wlo'.  A row-major [.., lda], W row-major [n][ldw].
// K elements streamed in chunks of 64.  smem: sA, sWhi, sWlo each 64*SPAD halves.
__device__ __forceinline__ void hgemm_acc(float accA[4][4], float accB[4][4],
                                          const __half* __restrict__ A, int lda,
                                          const __half* __restrict__ Whi,
                                          const __half* __restrict__ Wlo, int ldw,
                                          int K, int rbase, int nbase,
                                          __half* sA, __half* sWhi, __half* sWlo)
{
    const int tid = threadIdx.x;
    const int wid = tid >> 5, lane = tid & 31;
    const int gid = lane >> 2, tg = lane & 3;
    const int wm = wid >> 1, wn = wid & 1;
    const int nchunks = K >> 6;

    uint4 pa[2], pwh[2], pwl[2];
#pragma unroll
    for (int i = 0; i < 2; ++i) {
        int idx = i * 256 + tid;
        int row = idx >> 3, kg = idx & 7;
        int ke = kg * 8;
        pa[i]  = *(const uint4*)(A   + (size_t)(rbase + row) * lda + ke);
        pwh[i] = *(const uint4*)(Whi + (size_t)(nbase + row) * ldw + ke);
        pwl[i] = *(const uint4*)(Wlo + (size_t)(nbase + row) * ldw + ke);
    }

    for (int kc = 0; kc < nchunks; ++kc) {
        __syncthreads();
#pragma unroll
        for (int i = 0; i < 2; ++i) {
            int idx = i * 256 + tid;
            int row = idx >> 3, kg = idx & 7;
            int so = row * SPAD + kg * 8;
            *(uint4*)&sA[so]   = pa[i];
            *(uint4*)&sWhi[so] = pwh[i];
            *(uint4*)&sWlo[so] = pwl[i];
        }
        __syncthreads();

        if (kc + 1 < nchunks) {
            int k0 = (kc + 1) * 64;
#pragma unroll
            for (int i = 0; i < 2; ++i) {
                int idx = i * 256 + tid;
                int row = idx >> 3, kg = idx & 7;
                int ke = kg * 8;
                pa[i]  = *(const uint4*)(A   + (size_t)(rbase + row) * lda + k0 + ke);
                pwh[i] = *(const uint4*)(Whi + (size_t)(nbase + row) * ldw + k0 + ke);
                pwl[i] = *(const uint4*)(Wlo + (size_t)(nbase + row) * ldw + k0 + ke);
            }
        }

#pragma unroll
        for (int k4 = 0; k4 < 4; ++k4) {
            int kb = k4 * 16 + tg * 2;
            uint a[4];
            {
                int r = wm * 16 + gid;
                int base = r * SPAD + kb;
                a[0] = *(const uint*)&sA[base];
                a[1] = *(const uint*)&sA[base + 8 * SPAD];
                a[2] = *(const uint*)&sA[base + 8];
                a[3] = *(const uint*)&sA[base + 8 * SPAD + 8];
            }
            uint bhi[4][2], blo[4][2];
#pragma unroll
            for (int nf = 0; nf < 4; ++nf) {
                int n = wn * 32 + nf * 8 + gid;
                int base = n * SPAD + kb;
                bhi[nf][0] = *(const uint*)&sWhi[base];
                bhi[nf][1] = *(const uint*)&sWhi[base + 8];
                blo[nf][0] = *(const uint*)&sWlo[base];
                blo[nf][1] = *(const uint*)&sWlo[base + 8];
            }
#pragma unroll
            for (int nf = 0; nf < 4; ++nf) {
                mma16816h(accA[nf], a, bhi[nf]);
                mma16816h(accB[nf], a, blo[nf]);
            }
        }
    }
}

// ---------------- step 6: hmid16 = gelu(res16 @ W1^T + b1) ----------------
__global__ __launch_bounds__(256) void k_hgemm(const __half* __restrict__ A,
                                               const float* __restrict__ bias,
                                               __half* __restrict__ C)
{
    __shared__ __half sA[64 * SPAD], sWhi[64 * SPAD], sWlo[64 * SPAD];
    float accA[4][4] = {}, accB[4][4] = {};
    const int rbase = blockIdx.y * 64, nbase = blockIdx.x * 64;
    hgemm_acc(accA, accB, A, 512, g_p1hi, g_p1lo, 512, 512, rbase, nbase, sA, sWhi, sWlo);

    const int wid = threadIdx.x >> 5, lane = threadIdx.x & 31;
    const int gid = lane >> 2, tg = lane & 3;
    const int wm = wid >> 1, wn = wid & 1;
#pragma unroll
    for (int nf = 0; nf < 4; ++nf) {
        int cb = wn * 32 + nf * 8 + tg * 2;
        float b0 = bias[nbase + cb], b1 = bias[nbase + cb + 1];
        float d0 = geluf(accA[nf][0] + LSC * accB[nf][0] + b0);
        float d1 = geluf(accA[nf][1] + LSC * accB[nf][1] + b1);
        float d2 = geluf(accA[nf][2] + LSC * accB[nf][2] + b0);
        float d3 = geluf(accA[nf][3] + LSC * accB[nf][3] + b1);
        int r = rbase + wm * 16 + gid;
        *(__half2*)&C[(size_t)r * 1024 + nbase + cb]       = __floats2half2_rn(d0, d1);
        *(__half2*)&C[(size_t)(r + 8) * 1024 + nbase + cb] = __floats2half2_rn(d2, d3);
    }
}

// ---------------- step 7: logits -> out[b][v][t] ----------------
__global__ __launch_bounds__(256) void k_hproj(const __half* __restrict__ A,
                                               float* __restrict__ out)
{
    __shared__ __half sA[64 * SPAD], sWhi[64 * SPAD], sWlo[64 * SPAD];
    float accA[4][4] = {}, accB[4][4] = {};
    const int rbase = blockIdx.y * 64, nbase = blockIdx.x * 64;
    hgemm_acc(accA, accB, A, 1024, g_p2hi, g_p2lo, 1024, 1024, rbase, nbase, sA, sWhi, sWlo);

    const int wid = threadIdx.x >> 5, lane = threadIdx.x & 31;
    const int gid = lane >> 2, tg = lane & 3;
    const int wm = wid >> 1, wn = wid & 1;
#pragma unroll
    for (int nf = 0; nf < 4; ++nf) {
        int cb = wn * 32 + nf * 8 + tg * 2;
        int v0 = nbase + cb;
        float b0 = g_pb2[v0], b1 = g_pb2[v0 + 1];
        float d[2][2] = {{accA[nf][0] + LSC * accB[nf][0] + b0, accA[nf][1] + LSC * accB[nf][1] + b1},
                         {accA[nf][2] + LSC * accB[nf][2] + b0, accA[nf][3] + LSC * accB[nf][3] + b1}};
#pragma unroll
        for (int q = 0; q < 2; ++q) {
            int r = rbase + wm * 16 + gid + q * 8;
            int b = r / TSTEPS, t = r - b * TSTEPS;
#pragma unroll
            for (int c = 0; c < 2; ++c) {
                int v = v0 + c;
                if (v < VV)
                    out[((size_t)b * VV + v) * TSTEPS + t] = d[q][c];
            }
        }
    }
}

// ================= fp32 init path =================
__device__ __forceinline__ void gemm_acc32(ull acc[2][4],
                                           const float* __restrict__ A, int lda,
                                           const float* __restrict__ B, int ldb,
                                           int K, int rbase, int nbase, float* smem)
{
    float* As = smem;
    float* Bs = smem + 32 * 64;
    const int tid = threadIdx.x;
    const int tx = tid & 15, ty = tid >> 4;
    const int nchunks = K >> 5;

    float4 pa[2], pb[2];
#pragma unroll
    for (int i = 0; i < 2; ++i) {
        int idx = i * 256 + tid;
        int row = idx >> 3, kg = idx & 7;
        pa[i] = *(const float4*)(A + (size_t)(rbase + row) * lda + kg * 4);
        pb[i] = *(const float4*)(B + (size_t)(nbase + row) * ldb + kg * 4);
    }

    for (int kc = 0; kc < nchunks; ++kc) {
        __syncthreads();
#pragma unroll
        for (int i = 0; i < 2; ++i) {
            int idx = i * 256 + tid;
            int row = idx >> 3, kg = idx & 7;
            As[(kg * 4 + 0) * 64 + row] = pa[i].x;
            As[(kg * 4 + 1) * 64 + row] = pa[i].y;
            As[(kg * 4 + 2) * 64 + row] = pa[i].z;
            As[(kg * 4 + 3) * 64 + row] = pa[i].w;
            Bs[(kg * 4 + 0) * 64 + row] = pb[i].x;
            Bs[(kg * 4 + 1) * 64 + row] = pb[i].y;
            Bs[(kg * 4 + 2) * 64 + row] = pb[i].z;
            Bs[(kg * 4 + 3) * 64 + row] = pb[i].w;
        }
        __syncthreads();

        if (kc + 1 < nchunks) {
            int k0 = (kc + 1) * 32;
#pragma unroll
            for (int i = 0; i < 2; ++i) {
                int idx = i * 256 + tid;
                int row = idx >> 3, kg = idx & 7;
                pa[i] = *(const float4*)(A + (size_t)(rbase + row) * lda + k0 + kg * 4);
                pb[i] = *(const float4*)(B + (size_t)(nbase + row) * ldb + k0 + kg * 4);
            }
        }

#pragma unroll
        for (int k = 0; k < 32; ++k) {
            ull a0 = *(const ull*)&As[k * 64 + ty * 4 + 0];
            ull a1 = *(const ull*)&As[k * 64 + ty * 4 + 2];
            float4 wv = *(const float4*)&Bs[k * 64 + tx * 4];
            ull w0 = pk2(wv.x, wv.x), w1 = pk2(wv.y, wv.y);
            ull w2 = pk2(wv.z, wv.z), w3 = pk2(wv.w, wv.w);
            fma2(acc[0][0], a0, w0); fma2(acc[0][1], a0, w1); fma2(acc[0][2], a0, w2); fma2(acc[0][3], a0, w3);
            fma2(acc[1][0], a1, w0); fma2(acc[1][1], a1, w1); fma2(acc[1][2], a1, w2); fma2(acc[1][3], a1, w3);
        }
    }
    __syncthreads();
}

__global__ __launch_bounds__(256) void k_gemm64(const float* __restrict__ A, int lda,
                                                const float* __restrict__ B, int ldb,
                                                const float* __restrict__ bias,
                                                float* __restrict__ C, int ldc, int K)
{
    __shared__ float smem[2 * 32 * 64];
    ull acc[2][4] = {};
    const int rbase = blockIdx.y * 64;
    const int nbase = blockIdx.x * 64;
    gemm_acc32(acc, A, lda, B, ldb, K, rbase, nbase, smem);

    const int tx = threadIdx.x & 15, ty = threadIdx.x >> 4;
#pragma unroll
    for (int p = 0; p < 2; ++p) {
        int r = rbase + ty * 4 + 2 * p;
#pragma unroll
        for (int c = 0; c < 4; ++c) {
            int n = nbase + tx * 4 + c;
            float2 v = upk2(acc[p][c]);
            float bz = bias[n];
            C[(size_t)r * ldc + n]       = v.x + bz;
            C[(size_t)(r + 1) * ldc + n] = v.y + bz;
        }
    }
}

// ---------------- prep: LSTM weight split, biases, embed, zero c ----------------
__global__ void k_prep(const float* __restrict__ w_ih, const float* __restrict__ w_hh,
                       const float* __restrict__ b_ih, const float* __restrict__ b_hh,
                       const float* __restrict__ embed, const int* __restrict__ sidx)
{
    const size_t stride = (size_t)gridDim.x * blockDim.x;
    const size_t tid = (size_t)blockIdx.x * blockDim.x + threadIdx.x;
    const size_t nel = (size_t)3 * 2048 * 1024;
    for (size_t i = tid; i < nel; i += stride) {
        int k  = (int)(i & 1023);
        size_t np = i >> 10;
        int l  = (int)(np >> 11);
        int n2 = (int)(np & 2047);
        int jj = n2 >> 2, g = n2 & 3;
        int n  = g * 512 + jj;
        float w = (k < 512) ? w_ih[((size_t)l * 2048 + n) * 512 + k]
                            : w_hh[((size_t)l * 2048 + n) * 512 + (k - 512)];
        __half hi = __float2half(w);
        g_whi[i] = hi;
        g_wlo[i] = __float2half(4096.0f * (w - __half2float(hi)));
    }
    for (size_t i = tid; i < 3 * 2048; i += stride) {
        int l = (int)(i >> 11), n2 = (int)(i & 2047);
        int jj = n2 >> 2, g = n2 & 3;
        int n = g * 512 + jj;
        g_bcomb[i] = b_ih[(size_t)l * 2048 + n] + b_hh[(size_t)l * 2048 + n];
    }
    for (size_t i = tid; i < 512; i += stride)
        g_e[i] = __float2half(embed[(size_t)(*sidx) * 512 + i]);
    for (size_t i = tid; i < (size_t)3 * BH; i += stride) g_c[1][i] = 0.f;
}

// ---------------- prep2: projection weight splits (pw2 padded to 128 rows) ----------------
__global__ void k_prep2(const float* __restrict__ pw1, const float* __restrict__ pw2,
                        const float* __restrict__ pb2)
{
    const size_t stride = (size_t)gridDim.x * blockDim.x;
    const size_t tid = (size_t)blockIdx.x * blockDim.x + threadIdx.x;
    for (size_t i = tid; i < (size_t)1024 * 512; i += stride) {
        float w = pw1[i];
        __half hi = __float2half(w);
        g_p1hi[i] = hi;
        g_p1lo[i] = __float2half(4096.0f * (w - __half2float(hi)));
    }
    for (size_t i = tid; i < (size_t)128 * 1024; i += stride) {
        int n = (int)(i >> 10);
        float w = (n < VV) ? pw2[(size_t)n * 1024 + (i & 1023)] : 0.f;
        __half hi = __float2half(w);
        g_p2hi[i] = hi;
        g_p2lo[i] = __float2half(4096.0f * (w - __half2float(hi)));
    }
    for (size_t i = tid; i < 128; i += stride)
        g_pb2[i] = (i < VV) ? pb2[i] : 0.f;
}

// h0 fp32 -> fp16 for all 3 layers of activation buffer 1
__global__ void k_split0()
{
    const int stride = gridDim.x * blockDim.x;
    for (int i = blockIdx.x * blockDim.x + threadIdx.x; i < BH; i += stride) {
        __half v = __float2half(g_h0[i]);
#pragma unroll
        for (int l = 0; l < 3; ++l) g_a[(3 + l) * BH + i] = v;
    }
}

// ---------------- recurrent step: fp16 2-term weight-split mma GEMM + fused cell ----
__global__ __launch_bounds__(256) void k_step(int t, int l)
{
    __shared__ __half sA  [64 * SPAD];
    __shared__ __half sWhi[64 * SPAD];
    __shared__ __half sWlo[64 * SPAD];

    const int tid = threadIdx.x;
    const int wid = tid >> 5, lane = tid & 31;
    const int gid = lane >> 2, tg = lane & 3;
    const int wm = wid >> 1, wn = wid & 1;
    const int mt = blockIdx.x >> 5, jt = blockIdx.x & 31;
    const int rbase = mt * 64, nbase = jt * 64;
    const int wpar = t & 1, rpar = wpar ^ 1;

    const __half* Whi = g_whi + ((size_t)l * 2048 + nbase) * 1024;
    const __half* Wlo = g_wlo + ((size_t)l * 2048 + nbase) * 1024;

    const __half* Ax; int ldax;
    if (l == 0) {
        if (t == 0) { Ax = g_e; ldax = 0; }
        else        { Ax = g_a + (size_t)(rpar * 3 + 2) * BH + (size_t)rbase * 512; ldax = 512; }
    } else {
        Ax = g_a + (size_t)(wpar * 3 + l - 1) * BH + (size_t)rbase * 512; ldax = 512;
    }
    const __half* Ahh = g_a + (size_t)(rpar * 3 + l) * BH + (size_t)rbase * 512;

    float accA[4][4] = {}, accB[4][4] = {};

    uint4 pa[2], pwh[2], pwl[2];
#pragma unroll
    for (int i = 0; i < 2; ++i) {
        int idx = i * 256 + tid;
        int row = idx >> 3, kg = idx & 7;
        int ke = kg * 8;
        pa[i]  = *(const uint4*)(Ax  + (size_t)row * ldax + ke);
        pwh[i] = *(const uint4*)(Whi + (size_t)row * 1024 + ke);
        pwl[i] = *(const uint4*)(Wlo + (size_t)row * 1024 + ke);
    }

    for (int kc = 0; kc < 16; ++kc) {
        __syncthreads();
#pragma unroll
        for (int i = 0; i < 2; ++i) {
            int idx = i * 256 + tid;
            int row = idx >> 3, kg = idx & 7;
            int so = row * SPAD + kg * 8;
            *(uint4*)&sA[so]   = pa[i];
            *(uint4*)&sWhi[so] = pwh[i];
            *(uint4*)&sWlo[so] = pwl[i];
        }
        __syncthreads();

        if (kc + 1 < 16) {
            int kn = kc + 1;
            const __half* Ah; int lda_, koff;
            if (kn < 8) { Ah = Ax;  lda_ = ldax; koff = kn * 64; }
            else        { Ah = Ahh; lda_ = 512;  koff = kn * 64 - 512; }
            int kW = kn * 64;
#pragma unroll
            for (int i = 0; i < 2; ++i) {
                int idx = i * 256 + tid;
                int row = idx >> 3, kg = idx & 7;
                int ke = kg * 8;
                pa[i]  = *(const uint4*)(Ah  + (size_t)row * lda_ + koff + ke);
                pwh[i] = *(const uint4*)(Whi + (size_t)row * 1024 + kW + ke);
                pwl[i] = *(const uint4*)(Wlo + (size_t)row * 1024 + kW + ke);
            }
        }

#pragma unroll
        for (int k4 = 0; k4 < 4; ++k4) {
            int kb = k4 * 16 + tg * 2;
            uint a[4];
            {
                int r = wm * 16 + gid;
                int base = r * SPAD + kb;
                a[0] = *(const uint*)&sA[base];
                a[1] = *(const uint*)&sA[base + 8 * SPAD];
                a[2] = *(const uint*)&sA[base + 8];
                a[3] = *(const uint*)&sA[base + 8 * SPAD + 8];
            }
            uint bhi[4][2], blo[4][2];
#pragma unroll
            for (int nf = 0; nf < 4; ++nf) {
                int n = wn * 32 + nf * 8 + gid;
                int base = n * SPAD + kb;
                bhi[nf][0] = *(const uint*)&sWhi[base];
                bhi[nf][1] = *(const uint*)&sWhi[base + 8];
                blo[nf][0] = *(const uint*)&sWlo[base];
                blo[nf][1] = *(const uint*)&sWlo[base + 8];
            }
#pragma unroll
            for (int nf = 0; nf < 4; ++nf) {
                mma16816h(accA[nf], a, bhi[nf]);
                mma16816h(accB[nf], a, blo[nf]);
            }
        }
    }

    // ---------- fused LSTM cell epilogue ----------
    const float* cprev = g_c[rpar] + (size_t)l * BH;
    float* cnew = g_c[wpar] + (size_t)l * BH;
    __half* hout = g_a + (size_t)(wpar * 3 + l) * BH;

#pragma unroll
    for (int nf = 0; nf < 4; ++nf) {
        float d0 = accA[nf][0] + LSC * accB[nf][0];
        float d1 = accA[nf][1] + LSC * accB[nf][1];
        float d2 = accA[nf][2] + LSC * accB[nf][2];
        float d3 = accA[nf][3] + LSC * accB[nf][3];
        int cb = wn * 32 + nf * 8 + tg * 2;
        float b0 = g_bcomb[l * 2048 + nbase + cb];
        float b1 = g_bcomb[l * 2048 + nbase + cb + 1];
        d0 += b0; d1 += b1; d2 += b0; d3 += b1;
        float p0 = __shfl_xor_sync(0xffffffffu, d0, 1);
        float p1 = __shfl_xor_sync(0xffffffffu, d1, 1);
        float p2 = __shfl_xor_sync(0xffffffffu, d2, 1);
        float p3 = __shfl_xor_sync(0xffffffffu, d3, 1);
        int r = rbase + wm * 16 + gid + ((tg & 1) ? 8 : 0);
        float I, F, G, O;
        if ((tg & 1) == 0) { I = d0; F = d1; G = p0; O = p1; }
        else               { I = p2; F = p3; G = d2; O = d3; }
        int j = jt * 16 + (cb >> 2);
        float Is = sigf(I), Fs = sigf(F), Gt = tanhf(G), Os = sigf(O);
        float cp = cprev[(size_t)r * 512 + j];
        float cn = Fs * cp + Is * Gt;
        float hn = Os * tanhf(cn);
        cnew[(size_t)r * 512 + j] = cn;
        __half hn16 = __float2half(hn);
        hout[(size_t)r * 512 + j] = hn16;
        if (l == 2) g_res16[((size_t)r * TSTEPS + t) * 512 + j] = hn16;
    }
}

// ---------------- host launcher ----------------
extern "C" void kernel_launch(void* const* d_in, const int* in_sizes, int n_in,
                              void* d_out, int out_size)
{
    (void)in_sizes; (void)n_in; (void)out_size;
    const float* feat  = (const float*)d_in[0];
    const float* vw    = (const float*)d_in[1];
    const float* vb    = (const float*)d_in[2];
    const float* embed = (const float*)d_in[3];
    const float* w_ih  = (const float*)d_in[4];
    const float* w_hh  = (const float*)d_in[5];
    const float* b_ih  = (const float*)d_in[6];
    const float* b_hh  = (const float*)d_in[7];
    const float* pw1   = (const float*)d_in[8];
    const float* pb1   = (const float*)d_in[9];
    const float* pw2   = (const float*)d_in[10];
    const float* pb2   = (const float*)d_in[11];
    const int*   sidx  = (const int*)d_in[12];
    float* out = (float*)d_out;

    float *s_feat1, *s_h0;
    __half *s_res16, *s_hmid16;
    cudaGetSymbolAddress((void**)&s_feat1, g_feat1);
    cudaGetSymbolAddress((void**)&s_h0, g_h0);
    cudaGetSymbolAddress((void**)&s_res16, g_res16);
    cudaGetSymbolAddress((void**)&s_hmid16, g_hmid16);

    // 1) weight splits + biases + embed + zero c
    k_prep<<<512, 256>>>(w_ih, w_hh, b_ih, b_hh, embed, sidx);
    k_prep2<<<256, 256>>>(pw1, pw2, pb2);
    // 2) feat1 = feat @ Vw^T + vb
    k_gemm64<<<dim3(8, 4), 256>>>(feat, 512, vw, 512, vb, s_feat1, 512, 512);
    // 3) h0 = feat1 @ Vw^T + vb
    k_gemm64<<<dim3(8, 4), 256>>>(s_feat1, 512, vw, 512, vb, s_h0, 512, 512);
    // 4) h0 -> fp16 activation buffer 1 (all 3 layers)
    k_split0<<<256, 256>>>();
    // 5) 600 recurrent tensor-core iterations (stream order = sync)
    for (int t = 0; t < TSTEPS; ++t)
        for (int l = 0; l < LLAYERS; ++l)
            k_step<<<128, 256>>>(t, l);
    // 6) hmid16 = gelu(res16 @ W1^T + b1)   [fp16 2-term mma]
    k_hgemm<<<dim3(16, 800), 256>>>(s_res16, pb1, s_hmid16);
    // 7) logits -> out[b][v][t]             [fp16 2-term mma]
    k_hproj<<<dim3(2, 800), 256>>>(s_hmid16, out);
}

// round 14
// speedup vs baseline: 3.0421x; 1.0008x over previous
#include <cuda_runtime.h>
#include <cuda_fp16.h>
#include <math.h>

// Problem constants
#define BB 256
#define HH 512
#define LLAYERS 3
#define TSTEPS 200
#define VV 100
#define BH (256 * 512)

typedef unsigned long long ull;
typedef unsigned int uint;

// ---------------- device scratch (no allocations allowed) ----------------
__device__ __align__(16) __half g_whi[3u * 2048u * 1024u];  // LSTM weights hi fp16
__device__ __align__(16) __half g_wlo[3u * 2048u * 1024u];  // LSTM weights lo fp16 (x4096)
__device__ __align__(16) float g_bcomb[3 * 2048];           // b_ih + b_hh, gate-interleaved
__device__ __align__(16) __half g_a[2 * 3 * BH];            // activations fp16 (double-buffered)
__device__ __align__(16) __half g_e[512];                   // embed <sos> row fp16
__device__ __align__(16) float g_c[2][3 * BH];              // cell states fp32
__device__ __align__(16) float g_feat1[BB * HH];
__device__ __align__(16) float g_h0[BB * HH];
__device__ __align__(16) __half g_res16[256u * 200u * 512u];   // [b][t][h] fp16
__device__ __align__(16) __half g_hmid16[51200u * 1024u];      // fp16
__device__ __align__(16) __half g_p1hi[1024u * 512u];          // proj_w1 hi
__device__ __align__(16) __half g_p1lo[1024u * 512u];          // proj_w1 lo (x4096)
__device__ __align__(16) __half g_p2hi[128u * 1024u];          // proj_w2 hi, rows 100..127 zero
__device__ __align__(16) __half g_p2lo[128u * 1024u];          // proj_w2 lo (x4096), padded
__device__ __align__(16) float g_pb2[128];                     // b2 padded

// ---------------- helpers ----------------
__device__ __forceinline__ ull pk2(float a, float b) {
    ull r; asm("mov.b64 %0, {%1, %2};" : "=l"(r) : "f"(a), "f"(b)); return r;
}
__device__ __forceinline__ float2 upk2(ull v) {
    float2 r; asm("mov.b64 {%0, %1}, %2;" : "=f"(r.x), "=f"(r.y) : "l"(v)); return r;
}
__device__ __forceinline__ void fma2(ull& d, ull a, ull b) {
    asm("fma.rn.f32x2 %0, %1, %2, %0;" : "+l"(d) : "l"(a), "l"(b));
}
__device__ __forceinline__ float sigf(float x) { return 1.0f / (1.0f + expf(-x)); }
__device__ __forceinline__ float geluf(float x) { return 0.5f * x * (1.0f + erff(x * 0.70710678118654752f)); }

__device__ __forceinline__ void mma16816h(float d[4], const uint a[4], const uint b[2]) {
    asm volatile(
        "mma.sync.aligned.m16n8k16.row.col.f32.f16.f16.f32 "
        "{%0,%1,%2,%3}, {%4,%5,%6,%7}, {%8,%9}, {%0,%1,%2,%3};"
        : "+f"(d[0]), "+f"(d[1]), "+f"(d[2]), "+f"(d[3])
        : "r"(a[0]), "r"(a[1]), "r"(a[2]), "r"(a[3]), "r"(b[0]), "r"(b[1]));
}

#define SPAD 72
#define LSC (1.0f / 4096.0f)

// ---------------- generic fp16 2-term mainloop (64x64 tile, 256 thr, 8 warps) ----
// accA += A*Whi, accB += A*Wlo'.  A row-major [.., lda], W row-major [n][ldw].
// K elements streamed in chunks of 64.  smem: sA, sWhi, sWlo each 64*SPAD halves.
__device__ __forceinline__ void hgemm_acc(float accA[4][4], float accB[4][4],
                                          const __half* __restrict__ A, int lda,
                                          const __half* __restrict__ Whi,
                                          const __half* __restrict__ Wlo, int ldw,
                                          int K, int rbase, int nbase,
                                          __half* sA, __half* sWhi, __half* sWlo)
{
    const int tid = threadIdx.x;
    const int wid = tid >> 5, lane = tid & 31;
    const int gid = lane >> 2, tg = lane & 3;
    const int wm = wid >> 1, wn = wid & 1;
    const int nchunks = K >> 6;

    uint4 pa[2], pwh[2], pwl[2];
#pragma unroll
    for (int i = 0; i < 2; ++i) {
        int idx = i * 256 + tid;
        int row = idx >> 3, kg = idx & 7;
        int ke = kg * 8;
        pa[i]  = *(const uint4*)(A   + (size_t)(rbase + row) * lda + ke);
        pwh[i] = *(const uint4*)(Whi + (size_t)(nbase + row) * ldw + ke);
        pwl[i] = *(const uint4*)(Wlo + (size_t)(nbase + row) * ldw + ke);
    }

    for (int kc = 0; kc < nchunks; ++kc) {
        __syncthreads();
#pragma unroll
        for (int i = 0; i < 2; ++i) {
            int idx = i * 256 + tid;
            int row = idx >> 3, kg = idx & 7;
            int so = row * SPAD + kg * 8;
            *(uint4*)&sA[so]   = pa[i];
            *(uint4*)&sWhi[so] = pwh[i];
            *(uint4*)&sWlo[so] = pwl[i];
        }
        __syncthreads();

        if (kc + 1 < nchunks) {
            int k0 = (kc + 1) * 64;
#pragma unroll
            for (int i = 0; i < 2; ++i) {
                int idx = i * 256 + tid;
                int row = idx >> 3, kg = idx & 7;
                int ke = kg * 8;
                pa[i]  = *(const uint4*)(A   + (size_t)(rbase + row) * lda + k0 + ke);
                pwh[i] = *(const uint4*)(Whi + (size_t)(nbase + row) * ldw + k0 + ke);
                pwl[i] = *(const uint4*)(Wlo + (size_t)(nbase + row) * ldw + k0 + ke);
            }
        }

#pragma unroll
        for (int k4 = 0; k4 < 4; ++k4) {
            int kb = k4 * 16 + tg * 2;
            uint a[4];
            {
                int r = wm * 16 + gid;
                int base = r * SPAD + kb;
                a[0] = *(const uint*)&sA[base];
                a[1] = *(const uint*)&sA[base + 8 * SPAD];
                a[2] = *(const uint*)&sA[base + 8];
                a[3] = *(const uint*)&sA[base + 8 * SPAD + 8];
            }
            uint bhi[4][2], blo[4][2];
#pragma unroll
            for (int nf = 0; nf < 4; ++nf) {
                int n = wn * 32 + nf * 8 + gid;
                int base = n * SPAD + kb;
                bhi[nf][0] = *(const uint*)&sWhi[base];
                bhi[nf][1] = *(const uint*)&sWhi[base + 8];
                blo[nf][0] = *(const uint*)&sWlo[base];
                blo[nf][1] = *(const uint*)&sWlo[base + 8];
            }
#pragma unroll
            for (int nf = 0; nf < 4; ++nf) {
                mma16816h(accA[nf], a, bhi[nf]);
                mma16816h(accB[nf], a, blo[nf]);
            }
        }
    }
}

// ---------------- step 6: hmid16 = gelu(res16 @ W1^T + b1) ----------------
__global__ __launch_bounds__(256) void k_hgemm(const __half* __restrict__ A,
                                               const float* __restrict__ bias,
                                               __half* __restrict__ C)
{
    __shared__ __half sA[64 * SPAD], sWhi[64 * SPAD], sWlo[64 * SPAD];
    float accA[4][4] = {}, accB[4][4] = {};
    const int rbase = blockIdx.y * 64, nbase = blockIdx.x * 64;
    hgemm_acc(accA, accB, A, 512, g_p1hi, g_p1lo, 512, 512, rbase, nbase, sA, sWhi, sWlo);

    const int wid = threadIdx.x >> 5, lane = threadIdx.x & 31;
    const int gid = lane >> 2, tg = lane & 3;
    const int wm = wid >> 1, wn = wid & 1;
#pragma unroll
    for (int nf = 0; nf < 4; ++nf) {
        int cb = wn * 32 + nf * 8 + tg * 2;
        float b0 = bias[nbase + cb], b1 = bias[nbase + cb + 1];
        float d0 = geluf(accA[nf][0] + LSC * accB[nf][0] + b0);
        float d1 = geluf(accA[nf][1] + LSC * accB[nf][1] + b1);
        float d2 = geluf(accA[nf][2] + LSC * accB[nf][2] + b0);
        float d3 = geluf(accA[nf][3] + LSC * accB[nf][3] + b1);
        int r = rbase + wm * 16 + gid;
        *(__half2*)&C[(size_t)r * 1024 + nbase + cb]       = __floats2half2_rn(d0, d1);
        *(__half2*)&C[(size_t)(r + 8) * 1024 + nbase + cb] = __floats2half2_rn(d2, d3);
    }
}

// ---------------- step 7: logits -> out[b][v][t] ----------------
__global__ __launch_bounds__(256) void k_hproj(const __half* __restrict__ A,
                                               float* __restrict__ out)
{
    __shared__ __half sA[64 * SPAD], sWhi[64 * SPAD], sWlo[64 * SPAD];
    float accA[4][4] = {}, accB[4][4] = {};
    const int rbase = blockIdx.y * 64, nbase = blockIdx.x * 64;
    hgemm_acc(accA, accB, A, 1024, g_p2hi, g_p2lo, 1024, 1024, rbase, nbase, sA, sWhi, sWlo);

    const int wid = threadIdx.x >> 5, lane = threadIdx.x & 31;
    const int gid = lane >> 2, tg = lane & 3;
    const int wm = wid >> 1, wn = wid & 1;
#pragma unroll
    for (int nf = 0; nf < 4; ++nf) {
        int cb = wn * 32 + nf * 8 + tg * 2;
        int v0 = nbase + cb;
        float b0 = g_pb2[v0], b1 = g_pb2[v0 + 1];
        float d[2][2] = {{accA[nf][0] + LSC * accB[nf][0] + b0, accA[nf][1] + LSC * accB[nf][1] + b1},
                         {accA[nf][2] + LSC * accB[nf][2] + b0, accA[nf][3] + LSC * accB[nf][3] + b1}};
#pragma unroll
        for (int q = 0; q < 2; ++q) {
            int r = rbase + wm * 16 + gid + q * 8;
            int b = r / TSTEPS, t = r - b * TSTEPS;
#pragma unroll
            for (int c = 0; c < 2; ++c) {
                int v = v0 + c;
                if (v < VV)
                    out[((size_t)b * VV + v) * TSTEPS + t] = d[q][c];
            }
        }
    }
}

// ================= fp32 init path =================
__device__ __forceinline__ void gemm_acc32(ull acc[2][4],
                                           const float* __restrict__ A, int lda,
                                           const float* __restrict__ B, int ldb,
                                           int K, int rbase, int nbase, float* smem)
{
    float* As = smem;
    float* Bs = smem + 32 * 64;
    const int tid = threadIdx.x;
    const int tx = tid & 15, ty = tid >> 4;
    const int nchunks = K >> 5;

    float4 pa[2], pb[2];
#pragma unroll
    for (int i = 0; i < 2; ++i) {
        int idx = i * 256 + tid;
        int row = idx >> 3, kg = idx & 7;
        pa[i] = *(const float4*)(A + (size_t)(rbase + row) * lda + kg * 4);
        pb[i] = *(const float4*)(B + (size_t)(nbase + row) * ldb + kg * 4);
    }

    for (int kc = 0; kc < nchunks; ++kc) {
        __syncthreads();
#pragma unroll
        for (int i = 0; i < 2; ++i) {
            int idx = i * 256 + tid;
            int row = idx >> 3, kg = idx & 7;
            As[(kg * 4 + 0) * 64 + row] = pa[i].x;
            As[(kg * 4 + 1) * 64 + row] = pa[i].y;
            As[(kg * 4 + 2) * 64 + row] = pa[i].z;
            As[(kg * 4 + 3) * 64 + row] = pa[i].w;
            Bs[(kg * 4 + 0) * 64 + row] = pb[i].x;
            Bs[(kg * 4 + 1) * 64 + row] = pb[i].y;
            Bs[(kg * 4 + 2) * 64 + row] = pb[i].z;
            Bs[(kg * 4 + 3) * 64 + row] = pb[i].w;
        }
        __syncthreads();

        if (kc + 1 < nchunks) {
            int k0 = (kc + 1) * 32;
#pragma unroll
            for (int i = 0; i < 2; ++i) {
                int idx = i * 256 + tid;
                int row = idx >> 3, kg = idx & 7;
                pa[i] = *(const float4*)(A + (size_t)(rbase + row) * lda + k0 + kg * 4);
                pb[i] = *(const float4*)(B + (size_t)(nbase + row) * ldb + k0 + kg * 4);
            }
        }

#pragma unroll
        for (int k = 0; k < 32; ++k) {
            ull a0 = *(const ull*)&As[k * 64 + ty * 4 + 0];
            ull a1 = *(const ull*)&As[k * 64 + ty * 4 + 2];
            float4 wv = *(const float4*)&Bs[k * 64 + tx * 4];
            ull w0 = pk2(wv.x, wv.x), w1 = pk2(wv.y, wv.y);
            ull w2 = pk2(wv.z, wv.z), w3 = pk2(wv.w, wv.w);
            fma2(acc[0][0], a0, w0); fma2(acc[0][1], a0, w1); fma2(acc[0][2], a0, w2); fma2(acc[0][3], a0, w3);
            fma2(acc[1][0], a1, w0); fma2(acc[1][1], a1, w1); fma2(acc[1][2], a1, w2); fma2(acc[1][3], a1, w3);
        }
    }
    __syncthreads();
}

__global__ __launch_bounds__(256) void k_gemm64(const float* __restrict__ A, int lda,
                                                const float* __restrict__ B, int ldb,
                                                const float* __restrict__ bias,
                                                float* __restrict__ C, int ldc, int K)
{
    __shared__ float smem[2 * 32 * 64];
    ull acc[2][4] = {};
    const int rbase = blockIdx.y * 64;
    const int nbase = blockIdx.x * 64;
    gemm_acc32(acc, A, lda, B, ldb, K, rbase, nbase, smem);

    const int tx = threadIdx.x & 15, ty = threadIdx.x >> 4;
#pragma unroll
    for (int p = 0; p < 2; ++p) {
        int r = rbase + ty * 4 + 2 * p;
#pragma unroll
        for (int c = 0; c < 4; ++c) {
            int n = nbase + tx * 4 + c;
            float2 v = upk2(acc[p][c]);
            float bz = bias[n];
            C[(size_t)r * ldc + n]       = v.x + bz;
            C[(size_t)(r + 1) * ldc + n] = v.y + bz;
        }
    }
}

// ---------------- prep: LSTM weight split, biases, embed, zero c ----------------
__global__ void k_prep(const float* __restrict__ w_ih, const float* __restrict__ w_hh,
                       const float* __restrict__ b_ih, const float* __restrict__ b_hh,
                       const float* __restrict__ embed, const int* __restrict__ sidx)
{
    const size_t stride = (size_t)gridDim.x * blockDim.x;
    const size_t tid = (size_t)blockIdx.x * blockDim.x + threadIdx.x;
    const size_t nel = (size_t)3 * 2048 * 1024;
    for (size_t i = tid; i < nel; i += stride) {
        int k  = (int)(i & 1023);
        size_t np = i >> 10;
        int l  = (int)(np >> 11);
        int n2 = (int)(np & 2047);
        int jj = n2 >> 2, g = n2 & 3;
        int n  = g * 512 + jj;
        float w = (k < 512) ? w_ih[((size_t)l * 2048 + n) * 512 + k]
                            : w_hh[((size_t)l * 2048 + n) * 512 + (k - 512)];
        __half hi = __float2half(w);
        g_whi[i] = hi;
        g_wlo[i] = __float2half(4096.0f * (w - __half2float(hi)));
    }
    for (size_t i = tid; i < 3 * 2048; i += stride) {
        int l = (int)(i >> 11), n2 = (int)(i & 2047);
        int jj = n2 >> 2, g = n2 & 3;
        int n = g * 512 + jj;
        g_bcomb[i] = b_ih[(size_t)l * 2048 + n] + b_hh[(size_t)l * 2048 + n];
    }
    for (size_t i = tid; i < 512; i += stride)
        g_e[i] = __float2half(embed[(size_t)(*sidx) * 512 + i]);
    for (size_t i = tid; i < (size_t)3 * BH; i += stride) g_c[1][i] = 0.f;
}

// ---------------- prep2: projection weight splits (pw2 padded to 128 rows) ----------------
__global__ void k_prep2(const float* __restrict__ pw1, const float* __restrict__ pw2,
                        const float* __restrict__ pb2)
{
    const size_t stride = (size_t)gridDim.x * blockDim.x;
    const size_t tid = (size_t)blockIdx.x * blockDim.x + threadIdx.x;
    for (size_t i = tid; i < (size_t)1024 * 512; i += stride) {
        float w = pw1[i];
        __half hi = __float2half(w);
        g_p1hi[i] = hi;
        g_p1lo[i] = __float2half(4096.0f * (w - __half2float(hi)));
    }
    for (size_t i = tid; i < (size_t)128 * 1024; i += stride) {
        int n = (int)(i >> 10);
        float w = (n < VV) ? pw2[(size_t)n * 1024 + (i & 1023)] : 0.f;
        __half hi = __float2half(w);
        g_p2hi[i] = hi;
        g_p2lo[i] = __float2half(4096.0f * (w - __half2float(hi)));
    }
    for (size_t i = tid; i < 128; i += stride)
        g_pb2[i] = (i < VV) ? pb2[i] : 0.f;
}

// h0 fp32 -> fp16 for all 3 layers of activation buffer 1
__global__ void k_split0()
{
    const int stride = gridDim.x * blockDim.x;
    for (int i = blockIdx.x * blockDim.x + threadIdx.x; i < BH; i += stride) {
        __half v = __float2half(g_h0[i]);
#pragma unroll
        for (int l = 0; l < 3; ++l) g_a[(3 + l) * BH + i] = v;
    }
}

// ---------------- recurrent step: fp16 2-term weight-split mma GEMM + fused cell ----
__global__ __launch_bounds__(256) void k_step(int t, int l)
{
    __shared__ __half sA  [64 * SPAD];
    __shared__ __half sWhi[64 * SPAD];
    __shared__ __half sWlo[64 * SPAD];

    const int tid = threadIdx.x;
    const int wid = tid >> 5, lane = tid & 31;
    const int gid = lane >> 2, tg = lane & 3;
    const int wm = wid >> 1, wn = wid & 1;
    const int mt = blockIdx.x >> 5, jt = blockIdx.x & 31;
    const int rbase = mt * 64, nbase = jt * 64;
    const int wpar = t & 1, rpar = wpar ^ 1;

    const __half* Whi = g_whi + ((size_t)l * 2048 + nbase) * 1024;
    const __half* Wlo = g_wlo + ((size_t)l * 2048 + nbase) * 1024;

    const __half* Ax; int ldax;
    if (l == 0) {
        if (t == 0) { Ax = g_e; ldax = 0; }
        else        { Ax = g_a + (size_t)(rpar * 3 + 2) * BH + (size_t)rbase * 512; ldax = 512; }
    } else {
        Ax = g_a + (size_t)(wpar * 3 + l - 1) * BH + (size_t)rbase * 512; ldax = 512;
    }
    const __half* Ahh = g_a + (size_t)(rpar * 3 + l) * BH + (size_t)rbase * 512;

    float accA[4][4] = {}, accB[4][4] = {};

    uint4 pa[2], pwh[2], pwl[2];
#pragma unroll
    for (int i = 0; i < 2; ++i) {
        int idx = i * 256 + tid;
        int row = idx >> 3, kg = idx & 7;
        int ke = kg * 8;
        pa[i]  = *(const uint4*)(Ax  + (size_t)row * ldax + ke);
        pwh[i] = *(const uint4*)(Whi + (size_t)row * 1024 + ke);
        pwl[i] = *(const uint4*)(Wlo + (size_t)row * 1024 + ke);
    }

    for (int kc = 0; kc < 16; ++kc) {
        __syncthreads();
#pragma unroll
        for (int i = 0; i < 2; ++i) {
            int idx = i * 256 + tid;
            int row = idx >> 3, kg = idx & 7;
            int so = row * SPAD + kg * 8;
            *(uint4*)&sA[so]   = pa[i];
            *(uint4*)&sWhi[so] = pwh[i];
            *(uint4*)&sWlo[so] = pwl[i];
        }
        __syncthreads();

        if (kc + 1 < 16) {
            int kn = kc + 1;
            const __half* Ah; int lda_, koff;
            if (kn < 8) { Ah = Ax;  lda_ = ldax; koff = kn * 64; }
            else        { Ah = Ahh; lda_ = 512;  koff = kn * 64 - 512; }
            int kW = kn * 64;
#pragma unroll
            for (int i = 0; i < 2; ++i) {
                int idx = i * 256 + tid;
                int row = idx >> 3, kg = idx & 7;
                int ke = kg * 8;
                pa[i]  = *(const uint4*)(Ah  + (size_t)row * lda_ + koff + ke);
                pwh[i] = *(const uint4*)(Whi + (size_t)row * 1024 + kW + ke);
                pwl[i] = *(const uint4*)(Wlo + (size_t)row * 1024 + kW + ke);
            }
        }

#pragma unroll
        for (int k4 = 0; k4 < 4; ++k4) {
            int kb = k4 * 16 + tg * 2;
            uint a[4];
            {
                int r = wm * 16 + gid;
                int base = r * SPAD + kb;
                a[0] = *(const uint*)&sA[base];
                a[1] = *(const uint*)&sA[base + 8 * SPAD];
                a[2] = *(const uint*)&sA[base + 8];
                a[3] = *(const uint*)&sA[base + 8 * SPAD + 8];
            }
            uint bhi[4][2], blo[4][2];
#pragma unroll
            for (int nf = 0; nf < 4; ++nf) {
                int n = wn * 32 + nf * 8 + gid;
                int base = n * SPAD + kb;
                bhi[nf][0] = *(const uint*)&sWhi[base];
                bhi[nf][1] = *(const uint*)&sWhi[base + 8];
                blo[nf][0] = *(const uint*)&sWlo[base];
                blo[nf][1] = *(const uint*)&sWlo[base + 8];
            }
#pragma unroll
            for (int nf = 0; nf < 4; ++nf) {
                mma16816h(accA[nf], a, bhi[nf]);
                mma16816h(accB[nf], a, blo[nf]);
            }
        }
    }

    // ---------- fused LSTM cell epilogue ----------
    const float* cprev = g_c[rpar] + (size_t)l * BH;
    float* cnew = g_c[wpar] + (size_t)l * BH;
    __half* hout = g_a + (size_t)(wpar * 3 + l) * BH;

#pragma unroll
    for (int nf = 0; nf < 4; ++nf) {
        float d0 = accA[nf][0] + LSC * accB[nf][0];
        float d1 = accA[nf][1] + LSC * accB[nf][1];
        float d2 = accA[nf][2] + LSC * accB[nf][2];
        float d3 = accA[nf][3] + LSC * accB[nf][3];
        int cb = wn * 32 + nf * 8 + tg * 2;
        float b0 = g_bcomb[l * 2048 + nbase + cb];
        float b1 = g_bcomb[l * 2048 + nbase + cb + 1];
        d0 += b0; d1 += b1; d2 += b0; d3 += b1;
        float p0 = __shfl_xor_sync(0xffffffffu, d0, 1);
        float p1 = __shfl_xor_sync(0xffffffffu, d1, 1);
        float p2 = __shfl_xor_sync(0xffffffffu, d2, 1);
        float p3 = __shfl_xor_sync(0xffffffffu, d3, 1);
        int r = rbase + wm * 16 + gid + ((tg & 1) ? 8 : 0);
        float I, F, G, O;
        if ((tg & 1) == 0) { I = d0; F = d1; G = p0; O = p1; }
        else               { I = p2; F = p3; G = d2; O = d3; }
        int j = jt * 16 + (cb >> 2);
        float Is = sigf(I), Fs = sigf(F), Gt = tanhf(G), Os = sigf(O);
        float cp = cprev[(size_t)r * 512 + j];
        float cn = Fs * cp + Is * Gt;
        float hn = Os * tanhf(cn);
        cnew[(size_t)r * 512 + j] = cn;
        __half hn16 = __float2half(hn);
        hout[(size_t)r * 512 + j] = hn16;
        if (l == 2) g_res16[((size_t)r * TSTEPS + t) * 512 + j] = hn16;
    }
}

// ---------------- host launcher ----------------
extern "C" void kernel_launch(void* const* d_in, const int* in_sizes, int n_in,
                              void* d_out, int out_size)
{
    (void)in_sizes; (void)n_in; (void)out_size;
    const float* feat  = (const float*)d_in[0];
    const float* vw    = (const float*)d_in[1];
    const float* vb    = (const float*)d_in[2];
    const float* embed = (const float*)d_in[3];
    const float* w_ih  = (const float*)d_in[4];
    const float* w_hh  = (const float*)d_in[5];
    const float* b_ih  = (const float*)d_in[6];
    const float* b_hh  = (const float*)d_in[7];
    const float* pw1   = (const float*)d_in[8];
    const float* pb1   = (const float*)d_in[9];
    const float* pw2   = (const float*)d_in[10];
    const float* pb2   = (const float*)d_in[11];
    const int*   sidx  = (const int*)d_in[12];
    float* out = (float*)d_out;

    float *s_feat1, *s_h0;
    __half *s_res16, *s_hmid16;
    cudaGetSymbolAddress((void**)&s_feat1, g_feat1);
    cudaGetSymbolAddress((void**)&s_h0, g_h0);
    cudaGetSymbolAddress((void**)&s_res16, g_res16);
    cudaGetSymbolAddress((void**)&s_hmid16, g_hmid16);

    // 1) weight splits + biases + embed + zero c
    k_prep<<<512, 256>>>(w_ih, w_hh, b_ih, b_hh, embed, sidx);
    k_prep2<<<256, 256>>>(pw1, pw2, pb2);
    // 2) feat1 = feat @ Vw^T + vb
    k_gemm64<<<dim3(8, 4), 256>>>(feat, 512, vw, 512, vb, s_feat1, 512, 512);
    // 3) h0 = feat1 @ Vw^T + vb
    k_gemm64<<<dim3(8, 4), 256>>>(s_feat1, 512, vw, 512, vb, s_h0, 512, 512);
    // 4) h0 -> fp16 activation buffer 1 (all 3 layers)
    k_split0<<<256, 256>>>();
    // 5) 600 recurrent tensor-core iterations (stream order = sync)
    for (int t = 0; t < TSTEPS; ++t)
        for (int l = 0; l < LLAYERS; ++l)
            k_step<<<128, 256>>>(t, l);
    // 6) hmid16 = gelu(res16 @ W1^T + b1)   [fp16 2-term mma]
    k_hgemm<<<dim3(16, 800), 256>>>(s_res16, pb1, s_hmid16);
    // 7) logits -> out[b][v][t]             [fp16 2-term mma]
    k_hproj<<<dim3(2, 800), 256>>>(s_hmid16, out);
}

// round 15
// speedup vs baseline: 3.7708x; 1.2395x over previous
#include <cuda_runtime.h>
#include <cuda_fp16.h>
#include <math.h>

// Problem constants
#define BB 256
#define HH 512
#define LLAYERS 3
#define TSTEPS 200
#define VV 100
#define BH (256 * 512)

typedef unsigned long long ull;
typedef unsigned int uint;

// ---------------- device scratch (no allocations allowed) ----------------
__device__ __align__(16) __half g_whi[3u * 2048u * 1024u];  // LSTM weights fp16 (1-term)
__device__ __align__(16) float g_bcomb[3 * 2048];           // b_ih + b_hh, gate-interleaved
__device__ __align__(16) __half g_a[2 * 3 * BH];            // activations fp16 (double-buffered)
__device__ __align__(16) __half g_e[512];                   // embed <sos> row fp16
__device__ __align__(16) float g_c[2][3 * BH];              // cell states fp32
__device__ __align__(16) float g_feat1[BB * HH];
__device__ __align__(16) float g_h0[BB * HH];
__device__ __align__(16) __half g_res16[256u * 200u * 512u];   // [b][t][h] fp16
__device__ __align__(16) __half g_hmid16[51200u * 1024u];      // fp16
__device__ __align__(16) __half g_p1hi[1024u * 512u];          // proj_w1 hi
__device__ __align__(16) __half g_p1lo[1024u * 512u];          // proj_w1 lo (x4096)
__device__ __align__(16) __half g_p2hi[128u * 1024u];          // proj_w2 hi, rows 100..127 zero
__device__ __align__(16) __half g_p2lo[128u * 1024u];          // proj_w2 lo (x4096), padded
__device__ __align__(16) float g_pb2[128];                     // b2 padded

// ---------------- helpers ----------------
__device__ __forceinline__ ull pk2(float a, float b) {
    ull r; asm("mov.b64 %0, {%1, %2};" : "=l"(r) : "f"(a), "f"(b)); return r;
}
__device__ __forceinline__ float2 upk2(ull v) {
    float2 r; asm("mov.b64 {%0, %1}, %2;" : "=f"(r.x), "=f"(r.y) : "l"(v)); return r;
}
__device__ __forceinline__ void fma2(ull& d, ull a, ull b) {
    asm("fma.rn.f32x2 %0, %1, %2, %0;" : "+l"(d) : "l"(a), "l"(b));
}
__device__ __forceinline__ float sigf(float x) { return 1.0f / (1.0f + expf(-x)); }
__device__ __forceinline__ float geluf(float x) { return 0.5f * x * (1.0f + erff(x * 0.70710678118654752f)); }

__device__ __forceinline__ void mma16816h(float d[4], const uint a[4], const uint b[2]) {
    asm volatile(
        "mma.sync.aligned.m16n8k16.row.col.f32.f16.f16.f32 "
        "{%0,%1,%2,%3}, {%4,%5,%6,%7}, {%8,%9}, {%0,%1,%2,%3};"
        : "+f"(d[0]), "+f"(d[1]), "+f"(d[2]), "+f"(d[3])
        : "r"(a[0]), "r"(a[1]), "r"(a[2]), "r"(a[3]), "r"(b[0]), "r"(b[1]));
}

#define SPAD 72
#define LSC (1.0f / 4096.0f)

// ---------------- generic fp16 2-term mainloop (projection only) ----------------
__device__ __forceinline__ void hgemm_acc(float accA[4][4], float accB[4][4],
                                          const __half* __restrict__ A, int lda,
                                          const __half* __restrict__ Whi,
                                          const __half* __restrict__ Wlo, int ldw,
                                          int K, int rbase, int nbase,
                                          __half* sA, __half* sWhi, __half* sWlo)
{
    const int tid = threadIdx.x;
    const int wid = tid >> 5, lane = tid & 31;
    const int gid = lane >> 2, tg = lane & 3;
    const int wm = wid >> 1, wn = wid & 1;
    const int nchunks = K >> 6;

    uint4 pa[2], pwh[2], pwl[2];
#pragma unroll
    for (int i = 0; i < 2; ++i) {
        int idx = i * 256 + tid;
        int row = idx >> 3, kg = idx & 7;
        int ke = kg * 8;
        pa[i]  = *(const uint4*)(A   + (size_t)(rbase + row) * lda + ke);
        pwh[i] = *(const uint4*)(Whi + (size_t)(nbase + row) * ldw + ke);
        pwl[i] = *(const uint4*)(Wlo + (size_t)(nbase + row) * ldw + ke);
    }

    for (int kc = 0; kc < nchunks; ++kc) {
        __syncthreads();
#pragma unroll
        for (int i = 0; i < 2; ++i) {
            int idx = i * 256 + tid;
            int row = idx >> 3, kg = idx & 7;
            int so = row * SPAD + kg * 8;
            *(uint4*)&sA[so]   = pa[i];
            *(uint4*)&sWhi[so] = pwh[i];
            *(uint4*)&sWlo[so] = pwl[i];
        }
        __syncthreads();

        if (kc + 1 < nchunks) {
            int k0 = (kc + 1) * 64;
#pragma unroll
            for (int i = 0; i < 2; ++i) {
                int idx = i * 256 + tid;
                int row = idx >> 3, kg = idx & 7;
                int ke = kg * 8;
                pa[i]  = *(const uint4*)(A   + (size_t)(rbase + row) * lda + k0 + ke);
                pwh[i] = *(const uint4*)(Whi + (size_t)(nbase + row) * ldw + k0 + ke);
                pwl[i] = *(const uint4*)(Wlo + (size_t)(nbase + row) * ldw + k0 + ke);
            }
        }

#pragma unroll
        for (int k4 = 0; k4 < 4; ++k4) {
            int kb = k4 * 16 + tg * 2;
            uint a[4];
            {
                int r = wm * 16 + gid;
                int base = r * SPAD + kb;
                a[0] = *(const uint*)&sA[base];
                a[1] = *(const uint*)&sA[base + 8 * SPAD];
                a[2] = *(const uint*)&sA[base + 8];
                a[3] = *(const uint*)&sA[base + 8 * SPAD + 8];
            }
            uint bhi[4][2], blo[4][2];
#pragma unroll
            for (int nf = 0; nf < 4; ++nf) {
                int n = wn * 32 + nf * 8 + gid;
                int base = n * SPAD + kb;
                bhi[nf][0] = *(const uint*)&sWhi[base];
                bhi[nf][1] = *(const uint*)&sWhi[base + 8];
                blo[nf][0] = *(const uint*)&sWlo[base];
                blo[nf][1] = *(const uint*)&sWlo[base + 8];
            }
#pragma unroll
            for (int nf = 0; nf < 4; ++nf) {
                mma16816h(accA[nf], a, bhi[nf]);
                mma16816h(accB[nf], a, blo[nf]);
            }
        }
    }
}

// ---------------- step 6: hmid16 = gelu(res16 @ W1^T + b1) ----------------
__global__ __launch_bounds__(256) void k_hgemm(const __half* __restrict__ A,
                                               const float* __restrict__ bias,
                                               __half* __restrict__ C)
{
    __shared__ __half sA[64 * SPAD], sWhi[64 * SPAD], sWlo[64 * SPAD];
    float accA[4][4] = {}, accB[4][4] = {};
    const int rbase = blockIdx.y * 64, nbase = blockIdx.x * 64;
    hgemm_acc(accA, accB, A, 512, g_p1hi, g_p1lo, 512, 512, rbase, nbase, sA, sWhi, sWlo);

    const int wid = threadIdx.x >> 5, lane = threadIdx.x & 31;
    const int gid = lane >> 2, tg = lane & 3;
    const int wm = wid >> 1, wn = wid & 1;
#pragma unroll
    for (int nf = 0; nf < 4; ++nf) {
        int cb = wn * 32 + nf * 8 + tg * 2;
        float b0 = bias[nbase + cb], b1 = bias[nbase + cb + 1];
        float d0 = geluf(accA[nf][0] + LSC * accB[nf][0] + b0);
        float d1 = geluf(accA[nf][1] + LSC * accB[nf][1] + b1);
        float d2 = geluf(accA[nf][2] + LSC * accB[nf][2] + b0);
        float d3 = geluf(accA[nf][3] + LSC * accB[nf][3] + b1);
        int r = rbase + wm * 16 + gid;
        *(__half2*)&C[(size_t)r * 1024 + nbase + cb]       = __floats2half2_rn(d0, d1);
        *(__half2*)&C[(size_t)(r + 8) * 1024 + nbase + cb] = __floats2half2_rn(d2, d3);
    }
}

// ---------------- step 7: logits -> out[b][v][t] ----------------
__global__ __launch_bounds__(256) void k_hproj(const __half* __restrict__ A,
                                               float* __restrict__ out)
{
    __shared__ __half sA[64 * SPAD], sWhi[64 * SPAD], sWlo[64 * SPAD];
    float accA[4][4] = {}, accB[4][4] = {};
    const int rbase = blockIdx.y * 64, nbase = blockIdx.x * 64;
    hgemm_acc(accA, accB, A, 1024, g_p2hi, g_p2lo, 1024, 1024, rbase, nbase, sA, sWhi, sWlo);

    const int wid = threadIdx.x >> 5, lane = threadIdx.x & 31;
    const int gid = lane >> 2, tg = lane & 3;
    const int wm = wid >> 1, wn = wid & 1;
#pragma unroll
    for (int nf = 0; nf < 4; ++nf) {
        int cb = wn * 32 + nf * 8 + tg * 2;
        int v0 = nbase + cb;
        float b0 = g_pb2[v0], b1 = g_pb2[v0 + 1];
        float d[2][2] = {{accA[nf][0] + LSC * accB[nf][0] + b0, accA[nf][1] + LSC * accB[nf][1] + b1},
                         {accA[nf][2] + LSC * accB[nf][2] + b0, accA[nf][3] + LSC * accB[nf][3] + b1}};
#pragma unroll
        for (int q = 0; q < 2; ++q) {
            int r = rbase + wm * 16 + gid + q * 8;
            int b = r / TSTEPS, t = r - b * TSTEPS;
#pragma unroll
            for (int c = 0; c < 2; ++c) {
                int v = v0 + c;
                if (v < VV)
                    out[((size_t)b * VV + v) * TSTEPS + t] = d[q][c];
            }
        }
    }
}

// ================= fp32 init path =================
__device__ __forceinline__ void gemm_acc32(ull acc[2][4],
                                           const float* __restrict__ A, int lda,
                                           const float* __restrict__ B, int ldb,
                                           int K, int rbase, int nbase, float* smem)
{
    float* As = smem;
    float* Bs = smem + 32 * 64;
    const int tid = threadIdx.x;
    const int tx = tid & 15, ty = tid >> 4;
    const int nchunks = K >> 5;

    float4 pa[2], pb[2];
#pragma unroll
    for (int i = 0; i < 2; ++i) {
        int idx = i * 256 + tid;
        int row = idx >> 3, kg = idx & 7;
        pa[i] = *(const float4*)(A + (size_t)(rbase + row) * lda + kg * 4);
        pb[i] = *(const float4*)(B + (size_t)(nbase + row) * ldb + kg * 4);
    }

    for (int kc = 0; kc < nchunks; ++kc) {
        __syncthreads();
#pragma unroll
        for (int i = 0; i < 2; ++i) {
            int idx = i * 256 + tid;
            int row = idx >> 3, kg = idx & 7;
            As[(kg * 4 + 0) * 64 + row] = pa[i].x;
            As[(kg * 4 + 1) * 64 + row] = pa[i].y;
            As[(kg * 4 + 2) * 64 + row] = pa[i].z;
            As[(kg * 4 + 3) * 64 + row] = pa[i].w;
            Bs[(kg * 4 + 0) * 64 + row] = pb[i].x;
            Bs[(kg * 4 + 1) * 64 + row] = pb[i].y;
            Bs[(kg * 4 + 2) * 64 + row] = pb[i].z;
            Bs[(kg * 4 + 3) * 64 + row] = pb[i].w;
        }
        __syncthreads();

        if (kc + 1 < nchunks) {
            int k0 = (kc + 1) * 32;
#pragma unroll
            for (int i = 0; i < 2; ++i) {
                int idx = i * 256 + tid;
                int row = idx >> 3, kg = idx & 7;
                pa[i] = *(const float4*)(A + (size_t)(rbase + row) * lda + k0 + kg * 4);
                pb[i] = *(const float4*)(B + (size_t)(nbase + row) * ldb + k0 + kg * 4);
            }
        }

#pragma unroll
        for (int k = 0; k < 32; ++k) {
            ull a0 = *(const ull*)&As[k * 64 + ty * 4 + 0];
            ull a1 = *(const ull*)&As[k * 64 + ty * 4 + 2];
            float4 wv = *(const float4*)&Bs[k * 64 + tx * 4];
            ull w0 = pk2(wv.x, wv.x), w1 = pk2(wv.y, wv.y);
            ull w2 = pk2(wv.z, wv.z), w3 = pk2(wv.w, wv.w);
            fma2(acc[0][0], a0, w0); fma2(acc[0][1], a0, w1); fma2(acc[0][2], a0, w2); fma2(acc[0][3], a0, w3);
            fma2(acc[1][0], a1, w0); fma2(acc[1][1], a1, w1); fma2(acc[1][2], a1, w2); fma2(acc[1][3], a1, w3);
        }
    }
    __syncthreads();
}

__global__ __launch_bounds__(256) void k_gemm64(const float* __restrict__ A, int lda,
                                                const float* __restrict__ B, int ldb,
                                                const float* __restrict__ bias,
                                                float* __restrict__ C, int ldc, int K)
{
    __shared__ float smem[2 * 32 * 64];
    ull acc[2][4] = {};
    const int rbase = blockIdx.y * 64;
    const int nbase = blockIdx.x * 64;
    gemm_acc32(acc, A, lda, B, ldb, K, rbase, nbase, smem);

    const int tx = threadIdx.x & 15, ty = threadIdx.x >> 4;
#pragma unroll
    for (int p = 0; p < 2; ++p) {
        int r = rbase + ty * 4 + 2 * p;
#pragma unroll
        for (int c = 0; c < 4; ++c) {
            int n = nbase + tx * 4 + c;
            float2 v = upk2(acc[p][c]);
            float bz = bias[n];
            C[(size_t)r * ldc + n]       = v.x + bz;
            C[(size_t)(r + 1) * ldc + n] = v.y + bz;
        }
    }
}

// ---------------- prep: LSTM weight fp16 (1-term), biases, embed, zero c ----------------
__global__ void k_prep(const float* __restrict__ w_ih, const float* __restrict__ w_hh,
                       const float* __restrict__ b_ih, const float* __restrict__ b_hh,
                       const float* __restrict__ embed, const int* __restrict__ sidx)
{
    const size_t stride = (size_t)gridDim.x * blockDim.x;
    const size_t tid = (size_t)blockIdx.x * blockDim.x + threadIdx.x;
    const size_t nel = (size_t)3 * 2048 * 1024;
    for (size_t i = tid; i < nel; i += stride) {
        int k  = (int)(i & 1023);
        size_t np = i >> 10;
        int l  = (int)(np >> 11);
        int n2 = (int)(np & 2047);
        int jj = n2 >> 2, g = n2 & 3;
        int n  = g * 512 + jj;
        float w = (k < 512) ? w_ih[((size_t)l * 2048 + n) * 512 + k]
                            : w_hh[((size_t)l * 2048 + n) * 512 + (k - 512)];
        g_whi[i] = __float2half(w);
    }
    for (size_t i = tid; i < 3 * 2048; i += stride) {
        int l = (int)(i >> 11), n2 = (int)(i & 2047);
        int jj = n2 >> 2, g = n2 & 3;
        int n = g * 512 + jj;
        g_bcomb[i] = b_ih[(size_t)l * 2048 + n] + b_hh[(size_t)l * 2048 + n];
    }
    for (size_t i = tid; i < 512; i += stride)
        g_e[i] = __float2half(embed[(size_t)(*sidx) * 512 + i]);
    for (size_t i = tid; i < (size_t)3 * BH; i += stride) g_c[1][i] = 0.f;
}

// ---------------- prep2: projection weight splits (pw2 padded to 128 rows) ----------------
__global__ void k_prep2(const float* __restrict__ pw1, const float* __restrict__ pw2,
                        const float* __restrict__ pb2)
{
    const size_t stride = (size_t)gridDim.x * blockDim.x;
    const size_t tid = (size_t)blockIdx.x * blockDim.x + threadIdx.x;
    for (size_t i = tid; i < (size_t)1024 * 512; i += stride) {
        float w = pw1[i];
        __half hi = __float2half(w);
        g_p1hi[i] = hi;
        g_p1lo[i] = __float2half(4096.0f * (w - __half2float(hi)));
    }
    for (size_t i = tid; i < (size_t)128 * 1024; i += stride) {
        int n = (int)(i >> 10);
        float w = (n < VV) ? pw2[(size_t)n * 1024 + (i & 1023)] : 0.f;
        __half hi = __float2half(w);
        g_p2hi[i] = hi;
        g_p2lo[i] = __float2half(4096.0f * (w - __half2float(hi)));
    }
    for (size_t i = tid; i < 128; i += stride)
        g_pb2[i] = (i < VV) ? pb2[i] : 0.f;
}

// h0 fp32 -> fp16 for all 3 layers of activation buffer 1
__global__ void k_split0()
{
    const int stride = gridDim.x * blockDim.x;
    for (int i = blockIdx.x * blockDim.x + threadIdx.x; i < BH; i += stride) {
        __half v = __float2half(g_h0[i]);
#pragma unroll
        for (int l = 0; l < 3; ++l) g_a[(3 + l) * BH + i] = v;
    }
}

// ---------------- recurrent step: fp16 1-term mma GEMM + fused cell ----------------
// CTA tile M=64 x N=64, K=1024.  256 HMMA/warp/iter (half of 2-term).
__global__ __launch_bounds__(256) void k_step(int t, int l)
{
    __shared__ __half sA  [64 * SPAD];
    __shared__ __half sWhi[64 * SPAD];

    const int tid = threadIdx.x;
    const int wid = tid >> 5, lane = tid & 31;
    const int gid = lane >> 2, tg = lane & 3;
    const int wm = wid >> 1, wn = wid & 1;
    const int mt = blockIdx.x >> 5, jt = blockIdx.x & 31;
    const int rbase = mt * 64, nbase = jt * 64;
    const int wpar = t & 1, rpar = wpar ^ 1;

    const __half* Whi = g_whi + ((size_t)l * 2048 + nbase) * 1024;

    const __half* Ax; int ldax;
    if (l == 0) {
        if (t == 0) { Ax = g_e; ldax = 0; }
        else        { Ax = g_a + (size_t)(rpar * 3 + 2) * BH + (size_t)rbase * 512; ldax = 512; }
    } else {
        Ax = g_a + (size_t)(wpar * 3 + l - 1) * BH + (size_t)rbase * 512; ldax = 512;
    }
    const __half* Ahh = g_a + (size_t)(rpar * 3 + l) * BH + (size_t)rbase * 512;

    float accA[4][4] = {};

    uint4 pa[2], pwh[2];
#pragma unroll
    for (int i = 0; i < 2; ++i) {
        int idx = i * 256 + tid;
        int row = idx >> 3, kg = idx & 7;
        int ke = kg * 8;
        pa[i]  = *(const uint4*)(Ax  + (size_t)row * ldax + ke);
        pwh[i] = *(const uint4*)(Whi + (size_t)row * 1024 + ke);
    }

    for (int kc = 0; kc < 16; ++kc) {
        __syncthreads();
#pragma unroll
        for (int i = 0; i < 2; ++i) {
            int idx = i * 256 + tid;
            int row = idx >> 3, kg = idx & 7;
            int so = row * SPAD + kg * 8;
            *(uint4*)&sA[so]   = pa[i];
            *(uint4*)&sWhi[so] = pwh[i];
        }
        __syncthreads();

        if (kc + 1 < 16) {
            int kn = kc + 1;
            const __half* Ah; int lda_, koff;
            if (kn < 8) { Ah = Ax;  lda_ = ldax; koff = kn * 64; }
            else        { Ah = Ahh; lda_ = 512;  koff = kn * 64 - 512; }
            int kW = kn * 64;
#pragma unroll
            for (int i = 0; i < 2; ++i) {
                int idx = i * 256 + tid;
                int row = idx >> 3, kg = idx & 7;
                int ke = kg * 8;
                pa[i]  = *(const uint4*)(Ah  + (size_t)row * lda_ + koff + ke);
                pwh[i] = *(const uint4*)(Whi + (size_t)row * 1024 + kW + ke);
            }
        }

#pragma unroll
        for (int k4 = 0; k4 < 4; ++k4) {
            int kb = k4 * 16 + tg * 2;
            uint a[4];
            {
                int r = wm * 16 + gid;
                int base = r * SPAD + kb;
                a[0] = *(const uint*)&sA[base];
                a[1] = *(const uint*)&sA[base + 8 * SPAD];
                a[2] = *(const uint*)&sA[base + 8];
                a[3] = *(const uint*)&sA[base + 8 * SPAD + 8];
            }
            uint bhi[4][2];
#pragma unroll
            for (int nf = 0; nf < 4; ++nf) {
                int n = wn * 32 + nf * 8 + gid;
                int base = n * SPAD + kb;
                bhi[nf][0] = *(const uint*)&sWhi[base];
                bhi[nf][1] = *(const uint*)&sWhi[base + 8];
            }
#pragma unroll
            for (int nf = 0; nf < 4; ++nf)
                mma16816h(accA[nf], a, bhi[nf]);
        }
    }

    // ---------- fused LSTM cell epilogue ----------
    const float* cprev = g_c[rpar] + (size_t)l * BH;
    float* cnew = g_c[wpar] + (size_t)l * BH;
    __half* hout = g_a + (size_t)(wpar * 3 + l) * BH;

#pragma unroll
    for (int nf = 0; nf < 4; ++nf) {
        float d0 = accA[nf][0], d1 = accA[nf][1];
        float d2 = accA[nf][2], d3 = accA[nf][3];
        int cb = wn * 32 + nf * 8 + tg * 2;
        float b0 = g_bcomb[l * 2048 + nbase + cb];
        float b1 = g_bcomb[l * 2048 + nbase + cb + 1];
        d0 += b0; d1 += b1; d2 += b0; d3 += b1;
        float p0 = __shfl_xor_sync(0xffffffffu, d0, 1);
        float p1 = __shfl_xor_sync(0xffffffffu, d1, 1);
        float p2 = __shfl_xor_sync(0xffffffffu, d2, 1);
        float p3 = __shfl_xor_sync(0xffffffffu, d3, 1);
        int r = rbase + wm * 16 + gid + ((tg & 1) ? 8 : 0);
        float I, F, G, O;
        if ((tg & 1) == 0) { I = d0; F = d1; G = p0; O = p1; }
        else               { I = p2; F = p3; G = d2; O = d3; }
        int j = jt * 16 + (cb >> 2);
        float Is = sigf(I), Fs = sigf(F), Gt = tanhf(G), Os = sigf(O);
        float cp = cprev[(size_t)r * 512 + j];
        float cn = Fs * cp + Is * Gt;
        float hn = Os * tanhf(cn);
        cnew[(size_t)r * 512 + j] = cn;
        __half hn16 = __float2half(hn);
        hout[(size_t)r * 512 + j] = hn16;
        if (l == 2) g_res16[((size_t)r * TSTEPS + t) * 512 + j] = hn16;
    }
}

// ---------------- host launcher ----------------
extern "C" void kernel_launch(void* const* d_in, const int* in_sizes, int n_in,
                              void* d_out, int out_size)
{
    (void)in_sizes; (void)n_in; (void)out_size;
    const float* feat  = (const float*)d_in[0];
    const float* vw    = (const float*)d_in[1];
    const float* vb    = (const float*)d_in[2];
    const float* embed = (const float*)d_in[3];
    const float* w_ih  = (const float*)d_in[4];
    const float* w_hh  = (const float*)d_in[5];
    const float* b_ih  = (const float*)d_in[6];
    const float* b_hh  = (const float*)d_in[7];
    const float* pw1   = (const float*)d_in[8];
    const float* pb1   = (const float*)d_in[9];
    const float* pw2   = (const float*)d_in[10];
    const float* pb2   = (const float*)d_in[11];
    const int*   sidx  = (const int*)d_in[12];
    float* out = (float*)d_out;

    float *s_feat1, *s_h0;
    __half *s_res16, *s_hmid16;
    cudaGetSymbolAddress((void**)&s_feat1, g_feat1);
    cudaGetSymbolAddress((void**)&s_h0, g_h0);
    cudaGetSymbolAddress((void**)&s_res16, g_res16);
    cudaGetSymbolAddress((void**)&s_hmid16, g_hmid16);

    // 1) weight prep + biases + embed + zero c
    k_prep<<<512, 256>>>(w_ih, w_hh, b_ih, b_hh, embed, sidx);
    k_prep2<<<256, 256>>>(pw1, pw2, pb2);
    // 2) feat1 = feat @ Vw^T + vb
    k_gemm64<<<dim3(8, 4), 256>>>(feat, 512, vw, 512, vb, s_feat1, 512, 512);
    // 3) h0 = feat1 @ Vw^T + vb
    k_gemm64<<<dim3(8, 4), 256>>>(s_feat1, 512, vw, 512, vb, s_h0, 512, 512);
    // 4) h0 -> fp16 activation buffer 1 (all 3 layers)
    k_split0<<<256, 256>>>();
    // 5) 600 recurrent tensor-core iterations (stream order = sync)
    for (int t = 0; t < TSTEPS; ++t)
        for (int l = 0; l < LLAYERS; ++l)
            k_step<<<128, 256>>>(t, l);
    // 6) hmid16 = gelu(res16 @ W1^T + b1)   [fp16 2-term mma]
    k_hgemm<<<dim3(16, 800), 256>>>(s_res16, pb1, s_hmid16);
    // 7) logits -> out[b][v][t]             [fp16 2-term mma]
    k_hproj<<<dim3(2, 800), 256>>>(s_hmid16, out);
}